// round 11
// baseline (speedup 1.0000x reference)
#include <cuda_runtime.h>
#include <cuda_bf16.h>
#include <math.h>
#include <stdint.h>

// Problem constants
#define BB   2
#define SS   2048
#define DM   2048
#define NH   32
#define NKV  8
#define DH   64
#define MTOK (BB*SS)        // 4096 tokens

// ---------------------------------------------------------------------
// Scratch (device globals: allocation-free rule)
// ---------------------------------------------------------------------
__device__ __nv_bfloat16 g_Rh[MTOK * DM];
__device__ __nv_bfloat16 g_Rl[MTOK * DM];
__device__ __nv_bfloat16 g_WQh[2048 * DM];
__device__ __nv_bfloat16 g_WQl[2048 * DM];
__device__ __nv_bfloat16 g_WKh[512 * DM];
__device__ __nv_bfloat16 g_WKl[512 * DM];
__device__ __nv_bfloat16 g_WVh[512 * DM];
__device__ __nv_bfloat16 g_WVl[512 * DM];
__device__ __nv_bfloat16 g_WOTh[2048 * 2048];   // W_O transposed: [d][nh]
__device__ __nv_bfloat16 g_WOTl[2048 * 2048];

__device__ __nv_bfloat16 g_Qh[MTOK * (NH*DH)];
__device__ __nv_bfloat16 g_Ql[MTOK * (NH*DH)];
__device__ __nv_bfloat16 g_Kh[MTOK * (NKV*DH)];
__device__ __nv_bfloat16 g_Kl[MTOK * (NKV*DH)];
__device__ __nv_bfloat16 g_Vh[MTOK * (NKV*DH)];
__device__ __nv_bfloat16 g_Vl[MTOK * (NKV*DH)];

__device__ __nv_bfloat16 g_Ah[MTOK * (NH*DH)];
__device__ __nv_bfloat16 g_Al[MTOK * (NH*DH)];

// ---------------------------------------------------------------------
// helpers
// ---------------------------------------------------------------------
__device__ __forceinline__ uint32_t smem_u32(const void* p) {
    uint32_t a;
    asm("{ .reg .u64 t; cvta.to.shared.u64 t, %1; cvt.u32.u64 %0, t; }" : "=r"(a) : "l"(p));
    return a;
}
__device__ __forceinline__ void cp_async16(uint32_t dst, const void* src) {
    asm volatile("cp.async.cg.shared.global [%0], [%1], 16;" :: "r"(dst), "l"(src));
}
#define CP_COMMIT()  asm volatile("cp.async.commit_group;" ::: "memory")
#define CP_WAIT1()   asm volatile("cp.async.wait_group 1;" ::: "memory")

__device__ __forceinline__ void ldsm_x4(uint32_t addr, uint32_t& r0, uint32_t& r1,
                                        uint32_t& r2, uint32_t& r3) {
    asm volatile("ldmatrix.sync.aligned.m8n8.x4.shared.b16 {%0,%1,%2,%3}, [%4];"
                 : "=r"(r0), "=r"(r1), "=r"(r2), "=r"(r3) : "r"(addr));
}
__device__ __forceinline__ void ldsm_x4_t(uint32_t addr, uint32_t& r0, uint32_t& r1,
                                          uint32_t& r2, uint32_t& r3) {
    asm volatile("ldmatrix.sync.aligned.m8n8.x4.trans.shared.b16 {%0,%1,%2,%3}, [%4];"
                 : "=r"(r0), "=r"(r1), "=r"(r2), "=r"(r3) : "r"(addr));
}
__device__ __forceinline__ void mma_bf16(float* d, const uint32_t* a, uint32_t b0, uint32_t b1) {
    asm volatile(
        "mma.sync.aligned.m16n8k16.row.col.f32.bf16.bf16.f32 "
        "{%0,%1,%2,%3}, {%4,%5,%6,%7}, {%8,%9}, {%0,%1,%2,%3};"
        : "+f"(d[0]), "+f"(d[1]), "+f"(d[2]), "+f"(d[3])
        : "r"(a[0]), "r"(a[1]), "r"(a[2]), "r"(a[3]), "r"(b0), "r"(b1));
}
__device__ __forceinline__ float ex2(float x) {
    float y;
    asm("ex2.approx.f32 %0, %1;" : "=f"(y) : "f"(x));
    return y;
}
__device__ __forceinline__ void bsplit(float v, unsigned short& h, unsigned short& l) {
    __nv_bfloat16 bh = __float2bfloat16(v);
    float r = v - __bfloat162float(bh);
    __nv_bfloat16 bl = __float2bfloat16(r);
    h = *reinterpret_cast<unsigned short*>(&bh);
    l = *reinterpret_cast<unsigned short*>(&bl);
}
__device__ __forceinline__ uint32_t bf16_of(float v) {
    __nv_bfloat16 b = __float2bfloat16(v);
    return (uint32_t)*reinterpret_cast<unsigned short*>(&b);
}
__device__ __forceinline__ float bf16_back(uint32_t u) {
    unsigned short s = (unsigned short)u;
    return __bfloat162float(*reinterpret_cast<__nv_bfloat16*>(&s));
}

// ---------------------------------------------------------------------
// fp32 -> bf16 hi/lo split (inputs only)
// ---------------------------------------------------------------------
__global__ __launch_bounds__(256)
void split_kernel(const float* __restrict__ x, __nv_bfloat16* __restrict__ hi,
                  __nv_bfloat16* __restrict__ lo, int n4) {
    int i = blockIdx.x * 256 + threadIdx.x;
    if (i >= n4) return;
    float4 v = ((const float4*)x)[i];
    ushort4 h, l;
    bsplit(v.x, h.x, l.x); bsplit(v.y, h.y, l.y);
    bsplit(v.z, h.z, l.z); bsplit(v.w, h.w, l.w);
    ((ushort4*)hi)[i] = h;
    ((ushort4*)lo)[i] = l;
}

// W_O [nh=2048][d=2048] -> transposed split [d][nh]
__global__ __launch_bounds__(256)
void transpose_split_kernel(const float* __restrict__ W,
                            __nv_bfloat16* __restrict__ th,
                            __nv_bfloat16* __restrict__ tl) {
    __shared__ float t[32][33];
    int bx = blockIdx.x * 32, by = blockIdx.y * 32;
    int txx = threadIdx.x, tyy = threadIdx.y;   // block (32, 8)
    #pragma unroll
    for (int j = 0; j < 4; j++)
        t[tyy + 8*j][txx] = W[(size_t)(by + tyy + 8*j) * 2048 + bx + txx];
    __syncthreads();
    #pragma unroll
    for (int j = 0; j < 4; j++) {
        int orow = bx + tyy + 8*j;
        int ocol = by + txx;
        float v = t[txx][tyy + 8*j];
        unsigned short h, l;
        bsplit(v, h, l);
        th[(size_t)orow * 2048 + ocol] = *reinterpret_cast<__nv_bfloat16*>(&h);
        tl[(size_t)orow * 2048 + ocol] = *reinterpret_cast<__nv_bfloat16*>(&l);
    }
}

// ---------------------------------------------------------------------
// mma.sync bf16-split GEMM NT body (shared by QKV + O kernels)
// C[128,128] tile = A[128,K] @ B[128,K]^T, K=2048.
// ---------------------------------------------------------------------
#define BK        64
#define NKCHUNK   (DM / BK)          // 32
#define TILE_B    (128 * BK * 2)     // 16384
#define STG_B     (4 * TILE_B)       // 64KB
#define NSTAGE    3
#define GSMEM     (NSTAGE * STG_B)   // 192KB

template<int SPLIT_OUT>
__device__ __forceinline__
void gemm_body(const __nv_bfloat16* __restrict__ Ah, const __nv_bfloat16* __restrict__ Al,
               const __nv_bfloat16* __restrict__ Bh, const __nv_bfloat16* __restrict__ Bl,
               int row0, int col0,
               float* __restrict__ C, __nv_bfloat16* __restrict__ Ch,
               __nv_bfloat16* __restrict__ Cl, int Ntot) {
    extern __shared__ char sm[];
    const uint32_t sb = smem_u32(sm);
    const int tid = threadIdx.x, wid = tid >> 5, lane = tid & 31;
    const int wm = (wid >> 2) * 64;
    const int wn = (wid & 3) * 32;

    const char* gAh = (const char*)Ah + (size_t)row0 * 4096;
    const char* gAl = (const char*)Al + (size_t)row0 * 4096;
    const char* gBh = (const char*)Bh + (size_t)col0 * 4096;
    const char* gBl = (const char*)Bl + (size_t)col0 * 4096;

    const int lrow = ((lane >> 3) & 1) * 8 + (lane & 7);
    const int lkb  = (lane >> 4) * 16;

    float acc[4][4][4];
    #pragma unroll
    for (int mt = 0; mt < 4; mt++)
        #pragma unroll
        for (int nt = 0; nt < 4; nt++)
            #pragma unroll
            for (int e = 0; e < 4; e++) acc[mt][nt][e] = 0.f;

    auto load_stage = [&](int stage, int chunk) {
        uint32_t s0 = sb + stage * STG_B;
        const size_t kb0 = (size_t)chunk * 128;
        #pragma unroll
        for (int t = 0; t < 4; t++) {
            int idx = tid + t * 256;
            int r = idx >> 3, g = idx & 7;
            uint32_t so = (uint32_t)(r * 128 + ((g * 16) ^ ((r & 7) << 4)));
            size_t go = (size_t)r * 4096 + kb0 + g * 16;
            cp_async16(s0 + 0*TILE_B + so, gAh + go);
            cp_async16(s0 + 1*TILE_B + so, gAl + go);
            cp_async16(s0 + 2*TILE_B + so, gBh + go);
            cp_async16(s0 + 3*TILE_B + so, gBl + go);
        }
    };

    load_stage(0, 0); CP_COMMIT();
    load_stage(1, 1); CP_COMMIT();

    for (int i = 0; i < NKCHUNK; i++) {
        CP_WAIT1();
        __syncthreads();
        if (i + 2 < NKCHUNK) load_stage((i + 2) % NSTAGE, i + 2);
        CP_COMMIT();

        uint32_t s0 = sb + (i % NSTAGE) * STG_B;
        uint32_t aH = s0 + 0*TILE_B, aL = s0 + 1*TILE_B;
        uint32_t bH = s0 + 2*TILE_B, bL = s0 + 3*TILE_B;

        #pragma unroll
        for (int ks = 0; ks < 4; ks++) {
            const int kb = ks * 32 + lkb;
            uint32_t ah[4][4], al[4][4];
            #pragma unroll
            for (int mt = 0; mt < 4; mt++) {
                int r = wm + mt * 16 + lrow;
                uint32_t off = (uint32_t)(r * 128 + (kb ^ ((r & 7) << 4)));
                ldsm_x4(aH + off, ah[mt][0], ah[mt][1], ah[mt][2], ah[mt][3]);
                ldsm_x4(aL + off, al[mt][0], al[mt][1], al[mt][2], al[mt][3]);
            }
            uint32_t bhr[2][4], blr[2][4];
            #pragma unroll
            for (int np = 0; np < 2; np++) {
                int r = wn + np * 16 + lrow;
                uint32_t off = (uint32_t)(r * 128 + (kb ^ ((r & 7) << 4)));
                ldsm_x4(bH + off, bhr[np][0], bhr[np][1], bhr[np][2], bhr[np][3]);
                ldsm_x4(bL + off, blr[np][0], blr[np][1], blr[np][2], blr[np][3]);
            }
            #pragma unroll
            for (int mt = 0; mt < 4; mt++) {
                #pragma unroll
                for (int nt = 0; nt < 4; nt++) {
                    uint32_t b0h = bhr[nt >> 1][nt & 1], b1h = bhr[nt >> 1][2 + (nt & 1)];
                    uint32_t b0l = blr[nt >> 1][nt & 1], b1l = blr[nt >> 1][2 + (nt & 1)];
                    mma_bf16(acc[mt][nt], ah[mt], b0h, b1h);
                    mma_bf16(acc[mt][nt], ah[mt], b0l, b1l);
                    mma_bf16(acc[mt][nt], al[mt], b0h, b1h);
                }
            }
        }
        __syncthreads();
    }

    #pragma unroll
    for (int mt = 0; mt < 4; mt++) {
        int m0 = row0 + wm + mt * 16 + (lane >> 2);
        #pragma unroll
        for (int nt = 0; nt < 4; nt++) {
            int n0 = col0 + wn + nt * 8 + (lane & 3) * 2;
            if (SPLIT_OUT) {
                #pragma unroll
                for (int hh = 0; hh < 2; hh++) {
                    size_t idx = (size_t)(m0 + hh * 8) * Ntot + n0;
                    float v0 = acc[mt][nt][hh*2], v1 = acc[mt][nt][hh*2 + 1];
                    uint32_t h0 = bf16_of(v0), h1 = bf16_of(v1);
                    float r0 = v0 - bf16_back(h0), r1 = v1 - bf16_back(h1);
                    *(uint32_t*)&Ch[idx] = h0 | (h1 << 16);
                    *(uint32_t*)&Cl[idx] = bf16_of(r0) | (bf16_of(r1) << 16);
                }
            } else {
                *(float2*)&C[(size_t)m0 * Ntot + n0]       = make_float2(acc[mt][nt][0], acc[mt][nt][1]);
                *(float2*)&C[(size_t)(m0 + 8) * Ntot + n0] = make_float2(acc[mt][nt][2], acc[mt][nt][3]);
            }
        }
    }
}

// Merged QKV: grid (24, 32). col tiles 0-15 -> Q, 16-19 -> K, 20-23 -> V.
__global__ __launch_bounds__(256)
void gemm_qkv(const __nv_bfloat16* __restrict__ Rh, const __nv_bfloat16* __restrict__ Rl,
              const __nv_bfloat16* __restrict__ WQh, const __nv_bfloat16* __restrict__ WQl,
              const __nv_bfloat16* __restrict__ WKh, const __nv_bfloat16* __restrict__ WKl,
              const __nv_bfloat16* __restrict__ WVh, const __nv_bfloat16* __restrict__ WVl,
              __nv_bfloat16* __restrict__ Qh, __nv_bfloat16* __restrict__ Ql,
              __nv_bfloat16* __restrict__ Kh, __nv_bfloat16* __restrict__ Kl,
              __nv_bfloat16* __restrict__ Vh, __nv_bfloat16* __restrict__ Vl) {
    const int ct = blockIdx.x, row0 = blockIdx.y * 128;
    const __nv_bfloat16 *bh, *bl;
    __nv_bfloat16 *ch, *cl;
    int n, c0;
    if (ct < 16)      { bh = WQh; bl = WQl; ch = Qh; cl = Ql; n = 2048; c0 = ct * 128; }
    else if (ct < 20) { bh = WKh; bl = WKl; ch = Kh; cl = Kl; n = 512;  c0 = (ct - 16) * 128; }
    else              { bh = WVh; bl = WVl; ch = Vh; cl = Vl; n = 512;  c0 = (ct - 20) * 128; }
    gemm_body<1>(Rh, Rl, bh, bl, row0, c0, nullptr, ch, cl, n);
}

// O projection: fp32 output
__global__ __launch_bounds__(256)
void gemm_o(const __nv_bfloat16* __restrict__ Ah, const __nv_bfloat16* __restrict__ Al,
            const __nv_bfloat16* __restrict__ Bh, const __nv_bfloat16* __restrict__ Bl,
            float* __restrict__ C) {
    gemm_body<0>(Ah, Al, Bh, Bl, blockIdx.y * 128, blockIdx.x * 128, C, nullptr, nullptr, 2048);
}

// =====================================================================
// Tensor-core flash attention (causal, GQA, bf16 3-term split)
// Block: 128 Q rows x one head x one batch. 8 warps, warp = 16 Q rows.
// Heavy-first scheduling: qt = 15 - blockIdx.x (LPT packing).
// Softmax in exp2 domain (scale folds in log2e).
// =====================================================================
#define ATQ_H  0
#define ATQ_L  16384
#define ATSTG(s) (32768 + (s)*32768)
#define ATK_H  0
#define ATK_L  8192
#define ATV_H  16384
#define ATV_L  24576
#define ATSMEM 98304   // 96KB
#define SCALE2 0.18033688f   // 0.125 * log2(e)

__global__ __launch_bounds__(256)
void attn_mma(const __nv_bfloat16* __restrict__ Qh, const __nv_bfloat16* __restrict__ Ql,
              const __nv_bfloat16* __restrict__ Kh, const __nv_bfloat16* __restrict__ Kl,
              const __nv_bfloat16* __restrict__ Vh, const __nv_bfloat16* __restrict__ Vl,
              __nv_bfloat16* __restrict__ Oh, __nv_bfloat16* __restrict__ Ol) {
    extern __shared__ char sm[];
    const uint32_t sb = smem_u32(sm);
    const int tid = threadIdx.x, wid = tid >> 5, lane = tid & 31;
    const int qt = (int)gridDim.x - 1 - (int)blockIdx.x;   // heavy-first
    const int h = blockIdx.y, b = blockIdx.z;
    const int kvh = h >> 2;
    const int q0 = qt * 128;

    const char* gQh = (const char*)Qh + ((size_t)(b * SS + q0) * 2048 + h * 64) * 2;
    const char* gQl = (const char*)Ql + ((size_t)(b * SS + q0) * 2048 + h * 64) * 2;
    const char* gKh = (const char*)Kh + ((size_t)b * SS * 512 + kvh * 64) * 2;
    const char* gKl = (const char*)Kl + ((size_t)b * SS * 512 + kvh * 64) * 2;
    const char* gVh = (const char*)Vh + ((size_t)b * SS * 512 + kvh * 64) * 2;
    const char* gVl = (const char*)Vl + ((size_t)b * SS * 512 + kvh * 64) * 2;

    #pragma unroll
    for (int t = 0; t < 4; t++) {
        int idx = tid + t * 256;
        int r = idx >> 3, g = idx & 7;
        uint32_t so = (uint32_t)(r * 128 + ((g * 16) ^ ((r & 7) << 4)));
        cp_async16(sb + ATQ_H + so, gQh + (size_t)r * 4096 + g * 16);
        cp_async16(sb + ATQ_L + so, gQl + (size_t)r * 4096 + g * 16);
    }
    CP_COMMIT();

    auto load_kv = [&](int stage, int tile) {
        uint32_t s0 = sb + ATSTG(stage);
        #pragma unroll
        for (int t = 0; t < 2; t++) {
            int idx = tid + t * 256;
            int r = idx >> 3, g = idx & 7;
            uint32_t so = (uint32_t)(r * 128 + ((g * 16) ^ ((r & 7) << 4)));
            size_t go = (size_t)(tile * 64 + r) * 1024 + g * 16;
            cp_async16(s0 + ATK_H + so, gKh + go);
            cp_async16(s0 + ATK_L + so, gKl + go);
            cp_async16(s0 + ATV_H + so, gVh + go);
            cp_async16(s0 + ATV_L + so, gVl + go);
        }
    };

    const int ntiles = 2 * qt + 2;
    load_kv(0, 0); CP_COMMIT();

    CP_WAIT1();
    __syncthreads();

    const int lrow = ((lane >> 3) & 1) * 8 + (lane & 7);
    const int lkb  = (lane >> 4) * 16;
    uint32_t qfh[4][4], qfl[4][4];
    #pragma unroll
    for (int kc = 0; kc < 4; kc++) {
        int r = wid * 16 + lrow;
        uint32_t off = (uint32_t)(r * 128 + ((kc * 32 + lkb) ^ ((r & 7) << 4)));
        ldsm_x4(sb + ATQ_H + off, qfh[kc][0], qfh[kc][1], qfh[kc][2], qfh[kc][3]);
        ldsm_x4(sb + ATQ_L + off, qfl[kc][0], qfl[kc][1], qfl[kc][2], qfl[kc][3]);
    }

    load_kv(1, 1); CP_COMMIT();

    float m0 = -1e30f, m1 = -1e30f, l0 = 0.f, l1 = 0.f;
    float oacc[8][4];
    #pragma unroll
    for (int nt = 0; nt < 8; nt++)
        #pragma unroll
        for (int e = 0; e < 4; e++) oacc[nt][e] = 0.f;

    const int row0 = q0 + wid * 16 + (lane >> 2);
    const int row1 = row0 + 8;

    for (int j = 0; j < ntiles; j++) {
        CP_WAIT1();
        __syncthreads();

        uint32_t stg = sb + ATSTG(j & 1);

        // ---- S = Q K^T (3-term split) ----
        float sacc[8][4];
        #pragma unroll
        for (int nt = 0; nt < 8; nt++)
            #pragma unroll
            for (int e = 0; e < 4; e++) sacc[nt][e] = 0.f;

        #pragma unroll
        for (int kc = 0; kc < 4; kc++) {
            const int kb = kc * 32 + lkb;
            #pragma unroll
            for (int np = 0; np < 4; np++) {
                int r = np * 16 + lrow;
                uint32_t off = (uint32_t)(r * 128 + (kb ^ ((r & 7) << 4)));
                uint32_t kh0, kh1, kh2, kh3, kl0, kl1, kl2, kl3;
                ldsm_x4(stg + ATK_H + off, kh0, kh1, kh2, kh3);
                ldsm_x4(stg + ATK_L + off, kl0, kl1, kl2, kl3);
                mma_bf16(sacc[np*2+0], qfh[kc], kh0, kh2);
                mma_bf16(sacc[np*2+0], qfh[kc], kl0, kl2);
                mma_bf16(sacc[np*2+0], qfl[kc], kh0, kh2);
                mma_bf16(sacc[np*2+1], qfh[kc], kh1, kh3);
                mma_bf16(sacc[np*2+1], qfh[kc], kl1, kl3);
                mma_bf16(sacc[np*2+1], qfl[kc], kh1, kh3);
            }
        }

        // ---- scale (exp2 domain) + causal mask ----
        const int tok0 = j * 64;
        #pragma unroll
        for (int nt = 0; nt < 8; nt++)
            #pragma unroll
            for (int e = 0; e < 4; e++) sacc[nt][e] *= SCALE2;
        if (j >= 2 * qt) {
            #pragma unroll
            for (int nt = 0; nt < 8; nt++) {
                int colb = tok0 + nt * 8 + (lane & 3) * 2;
                if (colb     > row0) sacc[nt][0] = -1e30f;
                if (colb + 1 > row0) sacc[nt][1] = -1e30f;
                if (colb     > row1) sacc[nt][2] = -1e30f;
                if (colb + 1 > row1) sacc[nt][3] = -1e30f;
            }
        }

        // ---- online softmax (base-2) ----
        float mx0 = -1e30f, mx1 = -1e30f;
        #pragma unroll
        for (int nt = 0; nt < 8; nt++) {
            mx0 = fmaxf(mx0, fmaxf(sacc[nt][0], sacc[nt][1]));
            mx1 = fmaxf(mx1, fmaxf(sacc[nt][2], sacc[nt][3]));
        }
        mx0 = fmaxf(mx0, __shfl_xor_sync(0xffffffffu, mx0, 1));
        mx0 = fmaxf(mx0, __shfl_xor_sync(0xffffffffu, mx0, 2));
        mx1 = fmaxf(mx1, __shfl_xor_sync(0xffffffffu, mx1, 1));
        mx1 = fmaxf(mx1, __shfl_xor_sync(0xffffffffu, mx1, 2));
        float mn0 = fmaxf(m0, mx0), mn1 = fmaxf(m1, mx1);
        float a0 = ex2(m0 - mn0), a1 = ex2(m1 - mn1);
        m0 = mn0; m1 = mn1;

        float rs0 = 0.f, rs1 = 0.f;
        #pragma unroll
        for (int nt = 0; nt < 8; nt++) {
            sacc[nt][0] = ex2(sacc[nt][0] - mn0);
            sacc[nt][1] = ex2(sacc[nt][1] - mn0);
            sacc[nt][2] = ex2(sacc[nt][2] - mn1);
            sacc[nt][3] = ex2(sacc[nt][3] - mn1);
            rs0 += sacc[nt][0] + sacc[nt][1];
            rs1 += sacc[nt][2] + sacc[nt][3];
        }
        rs0 += __shfl_xor_sync(0xffffffffu, rs0, 1);
        rs0 += __shfl_xor_sync(0xffffffffu, rs0, 2);
        rs1 += __shfl_xor_sync(0xffffffffu, rs1, 1);
        rs1 += __shfl_xor_sync(0xffffffffu, rs1, 2);
        l0 = l0 * a0 + rs0;
        l1 = l1 * a1 + rs1;

        #pragma unroll
        for (int nt = 0; nt < 8; nt++) {
            oacc[nt][0] *= a0; oacc[nt][1] *= a0;
            oacc[nt][2] *= a1; oacc[nt][3] *= a1;
        }

        // ---- O += P V ----
        #pragma unroll
        for (int tc = 0; tc < 4; tc++) {
            uint32_t pfh[4], pfl[4];
            #pragma unroll
            for (int q = 0; q < 4; q++) {
                const int nt = tc * 2 + (q >> 1);
                const int e0 = (q & 1) * 2;
                float v0 = sacc[nt][e0], v1 = sacc[nt][e0 + 1];
                uint32_t h0 = bf16_of(v0), h1 = bf16_of(v1);
                int slot = (q >> 1) * 2 + (q & 1);
                pfh[slot] = h0 | (h1 << 16);
                pfl[slot] = bf16_of(v0 - bf16_back(h0)) | (bf16_of(v1 - bf16_back(h1)) << 16);
            }
            #pragma unroll
            for (int nh = 0; nh < 4; nh++) {
                int r = tc * 16 + lrow;
                uint32_t off = (uint32_t)(r * 128 + ((nh * 32 + lkb) ^ ((r & 7) << 4)));
                uint32_t vh0, vh1, vh2, vh3, vl0, vl1, vl2, vl3;
                ldsm_x4_t(stg + ATV_H + off, vh0, vh1, vh2, vh3);
                ldsm_x4_t(stg + ATV_L + off, vl0, vl1, vl2, vl3);
                mma_bf16(oacc[nh*2+0], pfh, vh0, vh1);
                mma_bf16(oacc[nh*2+0], pfh, vl0, vl1);
                mma_bf16(oacc[nh*2+0], pfl, vh0, vh1);
                mma_bf16(oacc[nh*2+1], pfh, vh2, vh3);
                mma_bf16(oacc[nh*2+1], pfh, vl2, vl3);
                mma_bf16(oacc[nh*2+1], pfl, vh2, vh3);
            }
        }

        __syncthreads();
        if (j + 2 < ntiles) load_kv(j & 1, j + 2);
        CP_COMMIT();
    }

    // ---- epilogue ----
    float inv0 = 1.f / l0, inv1 = 1.f / l1;
    #pragma unroll
    for (int nt = 0; nt < 8; nt++) {
        int col = nt * 8 + (lane & 3) * 2;
        #pragma unroll
        for (int hh = 0; hh < 2; hh++) {
            int grow = (hh == 0) ? row0 : row1;
            float inv = (hh == 0) ? inv0 : inv1;
            float v0 = oacc[nt][hh*2] * inv, v1 = oacc[nt][hh*2 + 1] * inv;
            size_t idx = (size_t)(b * SS + grow) * 2048 + h * 64 + col;
            uint32_t h0 = bf16_of(v0), h1 = bf16_of(v1);
            *(uint32_t*)&Oh[idx] = h0 | (h1 << 16);
            *(uint32_t*)&Ol[idx] = bf16_of(v0 - bf16_back(h0)) | (bf16_of(v1 - bf16_back(h1)) << 16);
        }
    }
}

// =====================================================================
// Host launcher
// =====================================================================
extern "C" void kernel_launch(void* const* d_in, const int* in_sizes, int n_in,
                              void* d_out, int out_size) {
    const float* residual = (const float*)d_in[0];
    const float* W_Q = (const float*)d_in[1];
    const float* W_K = (const float*)d_in[2];
    const float* W_V = (const float*)d_in[3];
    const float* W_O = (const float*)d_in[4];
    float* out = (float*)d_out;

    __nv_bfloat16 *Rh, *Rl, *WQh, *WQl, *WKh, *WKl, *WVh, *WVl, *WOTh, *WOTl;
    __nv_bfloat16 *Qh, *Ql, *Kh, *Kl, *Vh, *Vl, *Ah, *Al;
    cudaGetSymbolAddress((void**)&Rh,  g_Rh);   cudaGetSymbolAddress((void**)&Rl,  g_Rl);
    cudaGetSymbolAddress((void**)&WQh, g_WQh);  cudaGetSymbolAddress((void**)&WQl, g_WQl);
    cudaGetSymbolAddress((void**)&WKh, g_WKh);  cudaGetSymbolAddress((void**)&WKl, g_WKl);
    cudaGetSymbolAddress((void**)&WVh, g_WVh);  cudaGetSymbolAddress((void**)&WVl, g_WVl);
    cudaGetSymbolAddress((void**)&WOTh, g_WOTh); cudaGetSymbolAddress((void**)&WOTl, g_WOTl);
    cudaGetSymbolAddress((void**)&Qh, g_Qh);    cudaGetSymbolAddress((void**)&Ql, g_Ql);
    cudaGetSymbolAddress((void**)&Kh, g_Kh);    cudaGetSymbolAddress((void**)&Kl, g_Kl);
    cudaGetSymbolAddress((void**)&Vh, g_Vh);    cudaGetSymbolAddress((void**)&Vl, g_Vl);
    cudaGetSymbolAddress((void**)&Ah, g_Ah);    cudaGetSymbolAddress((void**)&Al, g_Al);

    cudaFuncSetAttribute(gemm_qkv, cudaFuncAttributeMaxDynamicSharedMemorySize, GSMEM);
    cudaFuncSetAttribute(gemm_o,   cudaFuncAttributeMaxDynamicSharedMemorySize, GSMEM);
    cudaFuncSetAttribute(attn_mma, cudaFuncAttributeMaxDynamicSharedMemorySize, ATSMEM);

    // fp32 -> bf16 hi/lo splits
    split_kernel<<<(MTOK*DM/4 + 255)/256, 256>>>(residual, Rh, Rl, MTOK*DM/4);
    split_kernel<<<(2048*DM/4 + 255)/256, 256>>>(W_Q, WQh, WQl, 2048*DM/4);
    split_kernel<<<(512*DM/4 + 255)/256, 256>>>(W_K, WKh, WKl, 512*DM/4);
    split_kernel<<<(512*DM/4 + 255)/256, 256>>>(W_V, WVh, WVl, 512*DM/4);
    transpose_split_kernel<<<dim3(64, 64), dim3(32, 8)>>>(W_O, WOTh, WOTl);

    // Merged QKV projections (single launch, 768 CTAs)
    gemm_qkv<<<dim3(24, MTOK/128), 256, GSMEM>>>(Rh, Rl, WQh, WQl, WKh, WKl, WVh, WVl,
                                                 Qh, Ql, Kh, Kl, Vh, Vl);

    // Tensor-core flash attention (heavy tiles first)
    attn_mma<<<dim3(SS/128, NH, BB), 256, ATSMEM>>>(Qh, Ql, Kh, Kl, Vh, Vl, Ah, Al);

    // Output projection -> fp32 out
    gemm_o<<<dim3(2048/128, MTOK/128), 256, GSMEM>>>(Ah, Al, WOTh, WOTl, out);
}

// round 13
// speedup vs baseline: 1.0394x; 1.0394x over previous
#include <cuda_runtime.h>
#include <cuda_bf16.h>
#include <math.h>
#include <stdint.h>

// Problem constants
#define BB   2
#define SS   2048
#define DM   2048
#define NH   32
#define NKV  8
#define DH   64
#define MTOK (BB*SS)        // 4096 tokens

// ---------------------------------------------------------------------
// Scratch (device globals: allocation-free rule)
// ---------------------------------------------------------------------
__device__ __nv_bfloat16 g_Rh[MTOK * DM];
__device__ __nv_bfloat16 g_Rl[MTOK * DM];
__device__ __nv_bfloat16 g_WQh[2048 * DM];
__device__ __nv_bfloat16 g_WQl[2048 * DM];
__device__ __nv_bfloat16 g_WKh[512 * DM];
__device__ __nv_bfloat16 g_WKl[512 * DM];
__device__ __nv_bfloat16 g_WVh[512 * DM];
__device__ __nv_bfloat16 g_WVl[512 * DM];
__device__ __nv_bfloat16 g_WOTh[2048 * 2048];   // W_O transposed: [d][nh]
__device__ __nv_bfloat16 g_WOTl[2048 * 2048];

__device__ __nv_bfloat16 g_Qh[MTOK * (NH*DH)];
__device__ __nv_bfloat16 g_Ql[MTOK * (NH*DH)];
__device__ __nv_bfloat16 g_Kh[MTOK * (NKV*DH)];
__device__ __nv_bfloat16 g_Kl[MTOK * (NKV*DH)];
__device__ __nv_bfloat16 g_Vh[MTOK * (NKV*DH)];
__device__ __nv_bfloat16 g_Vl[MTOK * (NKV*DH)];

__device__ __nv_bfloat16 g_Ah[MTOK * (NH*DH)];
__device__ __nv_bfloat16 g_Al[MTOK * (NH*DH)];

// ---------------------------------------------------------------------
// helpers
// ---------------------------------------------------------------------
__device__ __forceinline__ uint32_t smem_u32(const void* p) {
    uint32_t a;
    asm("{ .reg .u64 t; cvta.to.shared.u64 t, %1; cvt.u32.u64 %0, t; }" : "=r"(a) : "l"(p));
    return a;
}
__device__ __forceinline__ void cp_async16(uint32_t dst, const void* src) {
    asm volatile("cp.async.cg.shared.global [%0], [%1], 16;" :: "r"(dst), "l"(src));
}
#define CP_COMMIT()  asm volatile("cp.async.commit_group;" ::: "memory")
#define CP_WAIT1()   asm volatile("cp.async.wait_group 1;" ::: "memory")

__device__ __forceinline__ void ldsm_x4(uint32_t addr, uint32_t& r0, uint32_t& r1,
                                        uint32_t& r2, uint32_t& r3) {
    asm volatile("ldmatrix.sync.aligned.m8n8.x4.shared.b16 {%0,%1,%2,%3}, [%4];"
                 : "=r"(r0), "=r"(r1), "=r"(r2), "=r"(r3) : "r"(addr));
}
__device__ __forceinline__ void ldsm_x4_t(uint32_t addr, uint32_t& r0, uint32_t& r1,
                                          uint32_t& r2, uint32_t& r3) {
    asm volatile("ldmatrix.sync.aligned.m8n8.x4.trans.shared.b16 {%0,%1,%2,%3}, [%4];"
                 : "=r"(r0), "=r"(r1), "=r"(r2), "=r"(r3) : "r"(addr));
}
__device__ __forceinline__ void mma_bf16(float* d, const uint32_t* a, uint32_t b0, uint32_t b1) {
    asm volatile(
        "mma.sync.aligned.m16n8k16.row.col.f32.bf16.bf16.f32 "
        "{%0,%1,%2,%3}, {%4,%5,%6,%7}, {%8,%9}, {%0,%1,%2,%3};"
        : "+f"(d[0]), "+f"(d[1]), "+f"(d[2]), "+f"(d[3])
        : "r"(a[0]), "r"(a[1]), "r"(a[2]), "r"(a[3]), "r"(b0), "r"(b1));
}
__device__ __forceinline__ float ex2(float x) {
    float y;
    asm("ex2.approx.f32 %0, %1;" : "=f"(y) : "f"(x));
    return y;
}
// packed: returns {hi16=bf16(vhi), lo16=bf16(vlo)}
__device__ __forceinline__ uint32_t cvt_bf2(float vlo, float vhi) {
    uint32_t r;
    asm("cvt.rn.bf16x2.f32 %0, %1, %2;" : "=r"(r) : "f"(vhi), "f"(vlo));
    return r;
}
// split a pair: hi-packed word + residual-packed word
__device__ __forceinline__ void split_pair(float v0, float v1, uint32_t& ph, uint32_t& pl) {
    ph = cvt_bf2(v0, v1);
    float h0 = __uint_as_float(ph << 16);
    float h1 = __uint_as_float(ph & 0xffff0000u);
    pl = cvt_bf2(v0 - h0, v1 - h1);
}
__device__ __forceinline__ void bsplit(float v, unsigned short& h, unsigned short& l) {
    __nv_bfloat16 bh = __float2bfloat16(v);
    float r = v - __bfloat162float(bh);
    __nv_bfloat16 bl = __float2bfloat16(r);
    h = *reinterpret_cast<unsigned short*>(&bh);
    l = *reinterpret_cast<unsigned short*>(&bl);
}

// ---------------------------------------------------------------------
// fp32 -> bf16 hi/lo split (inputs only)
// ---------------------------------------------------------------------
__global__ __launch_bounds__(256)
void split_kernel(const float* __restrict__ x, __nv_bfloat16* __restrict__ hi,
                  __nv_bfloat16* __restrict__ lo, int n4) {
    int i = blockIdx.x * 256 + threadIdx.x;
    if (i >= n4) return;
    float4 v = ((const float4*)x)[i];
    ushort4 h, l;
    bsplit(v.x, h.x, l.x); bsplit(v.y, h.y, l.y);
    bsplit(v.z, h.z, l.z); bsplit(v.w, h.w, l.w);
    ((ushort4*)hi)[i] = h;
    ((ushort4*)lo)[i] = l;
}

// W_O [nh=2048][d=2048] -> transposed split [d][nh]
__global__ __launch_bounds__(256)
void transpose_split_kernel(const float* __restrict__ W,
                            __nv_bfloat16* __restrict__ th,
                            __nv_bfloat16* __restrict__ tl) {
    __shared__ float t[32][33];
    int bx = blockIdx.x * 32, by = blockIdx.y * 32;
    int txx = threadIdx.x, tyy = threadIdx.y;   // block (32, 8)
    #pragma unroll
    for (int j = 0; j < 4; j++)
        t[tyy + 8*j][txx] = W[(size_t)(by + tyy + 8*j) * 2048 + bx + txx];
    __syncthreads();
    #pragma unroll
    for (int j = 0; j < 4; j++) {
        int orow = bx + tyy + 8*j;
        int ocol = by + txx;
        float v = t[txx][tyy + 8*j];
        unsigned short h, l;
        bsplit(v, h, l);
        th[(size_t)orow * 2048 + ocol] = *reinterpret_cast<__nv_bfloat16*>(&h);
        tl[(size_t)orow * 2048 + ocol] = *reinterpret_cast<__nv_bfloat16*>(&l);
    }
}

// ---------------------------------------------------------------------
// mma.sync bf16-split GEMM NT body
// ---------------------------------------------------------------------
#define BK        64
#define NKCHUNK   (DM / BK)          // 32
#define TILE_B    (128 * BK * 2)     // 16384
#define STG_B     (4 * TILE_B)       // 64KB
#define NSTAGE    3
#define GSMEM     (NSTAGE * STG_B)   // 192KB

template<int SPLIT_OUT>
__device__ __forceinline__
void gemm_body(const __nv_bfloat16* __restrict__ Ah, const __nv_bfloat16* __restrict__ Al,
               const __nv_bfloat16* __restrict__ Bh, const __nv_bfloat16* __restrict__ Bl,
               int row0, int col0,
               float* __restrict__ C, __nv_bfloat16* __restrict__ Ch,
               __nv_bfloat16* __restrict__ Cl, int Ntot) {
    extern __shared__ char sm[];
    const uint32_t sb = smem_u32(sm);
    const int tid = threadIdx.x, wid = tid >> 5, lane = tid & 31;
    const int wm = (wid >> 2) * 64;
    const int wn = (wid & 3) * 32;

    const char* gAh = (const char*)Ah + (size_t)row0 * 4096;
    const char* gAl = (const char*)Al + (size_t)row0 * 4096;
    const char* gBh = (const char*)Bh + (size_t)col0 * 4096;
    const char* gBl = (const char*)Bl + (size_t)col0 * 4096;

    const int lrow = ((lane >> 3) & 1) * 8 + (lane & 7);
    const int lkb  = (lane >> 4) * 16;

    float acc[4][4][4];
    #pragma unroll
    for (int mt = 0; mt < 4; mt++)
        #pragma unroll
        for (int nt = 0; nt < 4; nt++)
            #pragma unroll
            for (int e = 0; e < 4; e++) acc[mt][nt][e] = 0.f;

    auto load_stage = [&](int stage, int chunk) {
        uint32_t s0 = sb + stage * STG_B;
        const size_t kb0 = (size_t)chunk * 128;
        #pragma unroll
        for (int t = 0; t < 4; t++) {
            int idx = tid + t * 256;
            int r = idx >> 3, g = idx & 7;
            uint32_t so = (uint32_t)(r * 128 + ((g * 16) ^ ((r & 7) << 4)));
            size_t go = (size_t)r * 4096 + kb0 + g * 16;
            cp_async16(s0 + 0*TILE_B + so, gAh + go);
            cp_async16(s0 + 1*TILE_B + so, gAl + go);
            cp_async16(s0 + 2*TILE_B + so, gBh + go);
            cp_async16(s0 + 3*TILE_B + so, gBl + go);
        }
    };

    load_stage(0, 0); CP_COMMIT();
    load_stage(1, 1); CP_COMMIT();

    for (int i = 0; i < NKCHUNK; i++) {
        CP_WAIT1();
        __syncthreads();
        if (i + 2 < NKCHUNK) load_stage((i + 2) % NSTAGE, i + 2);
        CP_COMMIT();

        uint32_t s0 = sb + (i % NSTAGE) * STG_B;
        uint32_t aH = s0 + 0*TILE_B, aL = s0 + 1*TILE_B;
        uint32_t bH = s0 + 2*TILE_B, bL = s0 + 3*TILE_B;

        #pragma unroll
        for (int ks = 0; ks < 4; ks++) {
            const int kb = ks * 32 + lkb;
            uint32_t ah[4][4], al[4][4];
            #pragma unroll
            for (int mt = 0; mt < 4; mt++) {
                int r = wm + mt * 16 + lrow;
                uint32_t off = (uint32_t)(r * 128 + (kb ^ ((r & 7) << 4)));
                ldsm_x4(aH + off, ah[mt][0], ah[mt][1], ah[mt][2], ah[mt][3]);
                ldsm_x4(aL + off, al[mt][0], al[mt][1], al[mt][2], al[mt][3]);
            }
            uint32_t bhr[2][4], blr[2][4];
            #pragma unroll
            for (int np = 0; np < 2; np++) {
                int r = wn + np * 16 + lrow;
                uint32_t off = (uint32_t)(r * 128 + (kb ^ ((r & 7) << 4)));
                ldsm_x4(bH + off, bhr[np][0], bhr[np][1], bhr[np][2], bhr[np][3]);
                ldsm_x4(bL + off, blr[np][0], blr[np][1], blr[np][2], blr[np][3]);
            }
            #pragma unroll
            for (int mt = 0; mt < 4; mt++) {
                #pragma unroll
                for (int nt = 0; nt < 4; nt++) {
                    uint32_t b0h = bhr[nt >> 1][nt & 1], b1h = bhr[nt >> 1][2 + (nt & 1)];
                    uint32_t b0l = blr[nt >> 1][nt & 1], b1l = blr[nt >> 1][2 + (nt & 1)];
                    mma_bf16(acc[mt][nt], ah[mt], b0h, b1h);
                    mma_bf16(acc[mt][nt], ah[mt], b0l, b1l);
                    mma_bf16(acc[mt][nt], al[mt], b0h, b1h);
                }
            }
        }
        __syncthreads();
    }

    #pragma unroll
    for (int mt = 0; mt < 4; mt++) {
        int m0 = row0 + wm + mt * 16 + (lane >> 2);
        #pragma unroll
        for (int nt = 0; nt < 4; nt++) {
            int n0 = col0 + wn + nt * 8 + (lane & 3) * 2;
            if (SPLIT_OUT) {
                #pragma unroll
                for (int hh = 0; hh < 2; hh++) {
                    size_t idx = (size_t)(m0 + hh * 8) * Ntot + n0;
                    uint32_t ph, pl;
                    split_pair(acc[mt][nt][hh*2], acc[mt][nt][hh*2 + 1], ph, pl);
                    *(uint32_t*)&Ch[idx] = ph;
                    *(uint32_t*)&Cl[idx] = pl;
                }
            } else {
                *(float2*)&C[(size_t)m0 * Ntot + n0]       = make_float2(acc[mt][nt][0], acc[mt][nt][1]);
                *(float2*)&C[(size_t)(m0 + 8) * Ntot + n0] = make_float2(acc[mt][nt][2], acc[mt][nt][3]);
            }
        }
    }
}

// Merged QKV: grid (24, 32). col tiles 0-15 -> Q, 16-19 -> K, 20-23 -> V.
__global__ __launch_bounds__(256)
void gemm_qkv(const __nv_bfloat16* __restrict__ Rh, const __nv_bfloat16* __restrict__ Rl,
              const __nv_bfloat16* __restrict__ WQh, const __nv_bfloat16* __restrict__ WQl,
              const __nv_bfloat16* __restrict__ WKh, const __nv_bfloat16* __restrict__ WKl,
              const __nv_bfloat16* __restrict__ WVh, const __nv_bfloat16* __restrict__ WVl,
              __nv_bfloat16* __restrict__ Qh, __nv_bfloat16* __restrict__ Ql,
              __nv_bfloat16* __restrict__ Kh, __nv_bfloat16* __restrict__ Kl,
              __nv_bfloat16* __restrict__ Vh, __nv_bfloat16* __restrict__ Vl) {
    const int ct = blockIdx.x, row0 = blockIdx.y * 128;
    const __nv_bfloat16 *bh, *bl;
    __nv_bfloat16 *ch, *cl;
    int n, c0;
    if (ct < 16)      { bh = WQh; bl = WQl; ch = Qh; cl = Ql; n = 2048; c0 = ct * 128; }
    else if (ct < 20) { bh = WKh; bl = WKl; ch = Kh; cl = Kl; n = 512;  c0 = (ct - 16) * 128; }
    else              { bh = WVh; bl = WVl; ch = Vh; cl = Vl; n = 512;  c0 = (ct - 20) * 128; }
    gemm_body<1>(Rh, Rl, bh, bl, row0, c0, nullptr, ch, cl, n);
}

// O projection: fp32 output
__global__ __launch_bounds__(256)
void gemm_o(const __nv_bfloat16* __restrict__ Ah, const __nv_bfloat16* __restrict__ Al,
            const __nv_bfloat16* __restrict__ Bh, const __nv_bfloat16* __restrict__ Bl,
            float* __restrict__ C) {
    gemm_body<0>(Ah, Al, Bh, Bl, blockIdx.y * 128, blockIdx.x * 128, C, nullptr, nullptr, 2048);
}

// =====================================================================
// Tensor-core flash attention (causal, GQA, bf16 3-term split)
// 128 Q rows per CTA, 8 warps x 16 rows. KV tiles of 64, double-buffered.
// Register-trimmed (Q frags reloaded from smem) + __launch_bounds__(256,2)
// to get 2 CTAs/SM so softmax overlaps MMA across CTAs.
// =====================================================================
#define ATQ_H  0
#define ATQ_L  16384
#define ATSTG(s) (32768 + (s)*32768)
#define ATK_H  0
#define ATK_L  8192
#define ATV_H  16384
#define ATV_L  24576
#define ATSMEM 98304   // 96KB -> 2 CTAs/SM = 192KB <= 228KB
#define SCALE2 0.18033688f   // 0.125 * log2(e)

__global__ __launch_bounds__(256, 2)
void attn_mma(const __nv_bfloat16* __restrict__ Qh, const __nv_bfloat16* __restrict__ Ql,
              const __nv_bfloat16* __restrict__ Kh, const __nv_bfloat16* __restrict__ Kl,
              const __nv_bfloat16* __restrict__ Vh, const __nv_bfloat16* __restrict__ Vl,
              __nv_bfloat16* __restrict__ Oh, __nv_bfloat16* __restrict__ Ol) {
    extern __shared__ char sm[];
    const uint32_t sb = smem_u32(sm);
    const int tid = threadIdx.x, wid = tid >> 5, lane = tid & 31;
    const int qt = (int)gridDim.x - 1 - (int)blockIdx.x;   // heavy-first
    const int h = blockIdx.y, b = blockIdx.z;
    const int kvh = h >> 2;
    const int q0 = qt * 128;

    const char* gQh = (const char*)Qh + ((size_t)(b * SS + q0) * 2048 + h * 64) * 2;
    const char* gQl = (const char*)Ql + ((size_t)(b * SS + q0) * 2048 + h * 64) * 2;
    const char* gKh = (const char*)Kh + ((size_t)b * SS * 512 + kvh * 64) * 2;
    const char* gKl = (const char*)Kl + ((size_t)b * SS * 512 + kvh * 64) * 2;
    const char* gVh = (const char*)Vh + ((size_t)b * SS * 512 + kvh * 64) * 2;
    const char* gVl = (const char*)Vl + ((size_t)b * SS * 512 + kvh * 64) * 2;

    #pragma unroll
    for (int t = 0; t < 4; t++) {
        int idx = tid + t * 256;
        int r = idx >> 3, g = idx & 7;
        uint32_t so = (uint32_t)(r * 128 + ((g * 16) ^ ((r & 7) << 4)));
        cp_async16(sb + ATQ_H + so, gQh + (size_t)r * 4096 + g * 16);
        cp_async16(sb + ATQ_L + so, gQl + (size_t)r * 4096 + g * 16);
    }
    CP_COMMIT();

    auto load_kv = [&](int stage, int tile) {
        uint32_t s0 = sb + ATSTG(stage);
        #pragma unroll
        for (int t = 0; t < 2; t++) {
            int idx = tid + t * 256;
            int r = idx >> 3, g = idx & 7;
            uint32_t so = (uint32_t)(r * 128 + ((g * 16) ^ ((r & 7) << 4)));
            size_t go = (size_t)(tile * 64 + r) * 1024 + g * 16;
            cp_async16(s0 + ATK_H + so, gKh + go);
            cp_async16(s0 + ATK_L + so, gKl + go);
            cp_async16(s0 + ATV_H + so, gVh + go);
            cp_async16(s0 + ATV_L + so, gVl + go);
        }
    };

    const int ntiles = 2 * qt + 2;
    load_kv(0, 0); CP_COMMIT();
    load_kv(1, 1); CP_COMMIT();

    float m0 = -1e30f, m1 = -1e30f, l0 = 0.f, l1 = 0.f;
    float oacc[8][4];
    #pragma unroll
    for (int nt = 0; nt < 8; nt++)
        #pragma unroll
        for (int e = 0; e < 4; e++) oacc[nt][e] = 0.f;

    const int lrow = ((lane >> 3) & 1) * 8 + (lane & 7);
    const int lkb  = (lane >> 4) * 16;
    const int row0 = q0 + wid * 16 + (lane >> 2);
    const int row1 = row0 + 8;
    const int qr = wid * 16 + lrow;

    for (int j = 0; j < ntiles; j++) {
        CP_WAIT1();
        __syncthreads();

        uint32_t stg = sb + ATSTG(j & 1);

        // ---- S = Q K^T (3-term split); Q frags reloaded from smem ----
        float sacc[8][4];
        #pragma unroll
        for (int nt = 0; nt < 8; nt++)
            #pragma unroll
            for (int e = 0; e < 4; e++) sacc[nt][e] = 0.f;

        #pragma unroll
        for (int kc = 0; kc < 4; kc++) {
            const int kb = kc * 32 + lkb;
            uint32_t qoff = (uint32_t)(qr * 128 + (kb ^ ((qr & 7) << 4)));
            uint32_t qh[4], ql[4];
            ldsm_x4(sb + ATQ_H + qoff, qh[0], qh[1], qh[2], qh[3]);
            ldsm_x4(sb + ATQ_L + qoff, ql[0], ql[1], ql[2], ql[3]);
            #pragma unroll
            for (int np = 0; np < 4; np++) {
                int r = np * 16 + lrow;
                uint32_t off = (uint32_t)(r * 128 + (kb ^ ((r & 7) << 4)));
                uint32_t kh0, kh1, kh2, kh3, kl0, kl1, kl2, kl3;
                ldsm_x4(stg + ATK_H + off, kh0, kh1, kh2, kh3);
                ldsm_x4(stg + ATK_L + off, kl0, kl1, kl2, kl3);
                mma_bf16(sacc[np*2+0], qh, kh0, kh2);
                mma_bf16(sacc[np*2+0], qh, kl0, kl2);
                mma_bf16(sacc[np*2+0], ql, kh0, kh2);
                mma_bf16(sacc[np*2+1], qh, kh1, kh3);
                mma_bf16(sacc[np*2+1], qh, kl1, kl3);
                mma_bf16(sacc[np*2+1], ql, kh1, kh3);
            }
        }

        // ---- scale (exp2 domain) + causal mask ----
        const int tok0 = j * 64;
        #pragma unroll
        for (int nt = 0; nt < 8; nt++)
            #pragma unroll
            for (int e = 0; e < 4; e++) sacc[nt][e] *= SCALE2;
        if (j >= 2 * qt) {
            #pragma unroll
            for (int nt = 0; nt < 8; nt++) {
                int colb = tok0 + nt * 8 + (lane & 3) * 2;
                if (colb     > row0) sacc[nt][0] = -1e30f;
                if (colb + 1 > row0) sacc[nt][1] = -1e30f;
                if (colb     > row1) sacc[nt][2] = -1e30f;
                if (colb + 1 > row1) sacc[nt][3] = -1e30f;
            }
        }

        // ---- online softmax (base-2) ----
        float mx0 = -1e30f, mx1 = -1e30f;
        #pragma unroll
        for (int nt = 0; nt < 8; nt++) {
            mx0 = fmaxf(mx0, fmaxf(sacc[nt][0], sacc[nt][1]));
            mx1 = fmaxf(mx1, fmaxf(sacc[nt][2], sacc[nt][3]));
        }
        mx0 = fmaxf(mx0, __shfl_xor_sync(0xffffffffu, mx0, 1));
        mx0 = fmaxf(mx0, __shfl_xor_sync(0xffffffffu, mx0, 2));
        mx1 = fmaxf(mx1, __shfl_xor_sync(0xffffffffu, mx1, 1));
        mx1 = fmaxf(mx1, __shfl_xor_sync(0xffffffffu, mx1, 2));
        float mn0 = fmaxf(m0, mx0), mn1 = fmaxf(m1, mx1);
        float a0 = ex2(m0 - mn0), a1 = ex2(m1 - mn1);
        m0 = mn0; m1 = mn1;

        float rs0 = 0.f, rs1 = 0.f;
        #pragma unroll
        for (int nt = 0; nt < 8; nt++) {
            sacc[nt][0] = ex2(sacc[nt][0] - mn0);
            sacc[nt][1] = ex2(sacc[nt][1] - mn0);
            sacc[nt][2] = ex2(sacc[nt][2] - mn1);
            sacc[nt][3] = ex2(sacc[nt][3] - mn1);
            rs0 += sacc[nt][0] + sacc[nt][1];
            rs1 += sacc[nt][2] + sacc[nt][3];
        }
        rs0 += __shfl_xor_sync(0xffffffffu, rs0, 1);
        rs0 += __shfl_xor_sync(0xffffffffu, rs0, 2);
        rs1 += __shfl_xor_sync(0xffffffffu, rs1, 1);
        rs1 += __shfl_xor_sync(0xffffffffu, rs1, 2);
        l0 = l0 * a0 + rs0;
        l1 = l1 * a1 + rs1;

        #pragma unroll
        for (int nt = 0; nt < 8; nt++) {
            oacc[nt][0] *= a0; oacc[nt][1] *= a0;
            oacc[nt][2] *= a1; oacc[nt][3] *= a1;
        }

        // ---- O += P V (packed bf16x2 split of P) ----
        #pragma unroll
        for (int tc = 0; tc < 4; tc++) {
            uint32_t pfh[4], pfl[4];
            #pragma unroll
            for (int q = 0; q < 4; q++) {
                const int nt = tc * 2 + (q >> 1);
                const int e0 = (q & 1) * 2;
                int slot = (q >> 1) * 2 + (q & 1);
                split_pair(sacc[nt][e0], sacc[nt][e0 + 1], pfh[slot], pfl[slot]);
            }
            #pragma unroll
            for (int nh = 0; nh < 4; nh++) {
                int r = tc * 16 + lrow;
                uint32_t off = (uint32_t)(r * 128 + ((nh * 32 + lkb) ^ ((r & 7) << 4)));
                uint32_t vh0, vh1, vh2, vh3, vl0, vl1, vl2, vl3;
                ldsm_x4_t(stg + ATV_H + off, vh0, vh1, vh2, vh3);
                ldsm_x4_t(stg + ATV_L + off, vl0, vl1, vl2, vl3);
                mma_bf16(oacc[nh*2+0], pfh, vh0, vh1);
                mma_bf16(oacc[nh*2+0], pfh, vl0, vl1);
                mma_bf16(oacc[nh*2+0], pfl, vh0, vh1);
                mma_bf16(oacc[nh*2+1], pfh, vh2, vh3);
                mma_bf16(oacc[nh*2+1], pfh, vl2, vl3);
                mma_bf16(oacc[nh*2+1], pfl, vh2, vh3);
            }
        }

        __syncthreads();
        if (j + 2 < ntiles) load_kv(j & 1, j + 2);
        CP_COMMIT();
    }

    // ---- epilogue (packed split) ----
    float inv0 = 1.f / l0, inv1 = 1.f / l1;
    #pragma unroll
    for (int nt = 0; nt < 8; nt++) {
        int col = nt * 8 + (lane & 3) * 2;
        #pragma unroll
        for (int hh = 0; hh < 2; hh++) {
            int grow = (hh == 0) ? row0 : row1;
            float inv = (hh == 0) ? inv0 : inv1;
            size_t idx = (size_t)(b * SS + grow) * 2048 + h * 64 + col;
            uint32_t ph, pl;
            split_pair(oacc[nt][hh*2] * inv, oacc[nt][hh*2 + 1] * inv, ph, pl);
            *(uint32_t*)&Oh[idx] = ph;
            *(uint32_t*)&Ol[idx] = pl;
        }
    }
}

// =====================================================================
// Host launcher
// =====================================================================
extern "C" void kernel_launch(void* const* d_in, const int* in_sizes, int n_in,
                              void* d_out, int out_size) {
    const float* residual = (const float*)d_in[0];
    const float* W_Q = (const float*)d_in[1];
    const float* W_K = (const float*)d_in[2];
    const float* W_V = (const float*)d_in[3];
    const float* W_O = (const float*)d_in[4];
    float* out = (float*)d_out;

    __nv_bfloat16 *Rh, *Rl, *WQh, *WQl, *WKh, *WKl, *WVh, *WVl, *WOTh, *WOTl;
    __nv_bfloat16 *Qh, *Ql, *Kh, *Kl, *Vh, *Vl, *Ah, *Al;
    cudaGetSymbolAddress((void**)&Rh,  g_Rh);   cudaGetSymbolAddress((void**)&Rl,  g_Rl);
    cudaGetSymbolAddress((void**)&WQh, g_WQh);  cudaGetSymbolAddress((void**)&WQl, g_WQl);
    cudaGetSymbolAddress((void**)&WKh, g_WKh);  cudaGetSymbolAddress((void**)&WKl, g_WKl);
    cudaGetSymbolAddress((void**)&WVh, g_WVh);  cudaGetSymbolAddress((void**)&WVl, g_WVl);
    cudaGetSymbolAddress((void**)&WOTh, g_WOTh); cudaGetSymbolAddress((void**)&WOTl, g_WOTl);
    cudaGetSymbolAddress((void**)&Qh, g_Qh);    cudaGetSymbolAddress((void**)&Ql, g_Ql);
    cudaGetSymbolAddress((void**)&Kh, g_Kh);    cudaGetSymbolAddress((void**)&Kl, g_Kl);
    cudaGetSymbolAddress((void**)&Vh, g_Vh);    cudaGetSymbolAddress((void**)&Vl, g_Vl);
    cudaGetSymbolAddress((void**)&Ah, g_Ah);    cudaGetSymbolAddress((void**)&Al, g_Al);

    cudaFuncSetAttribute(gemm_qkv, cudaFuncAttributeMaxDynamicSharedMemorySize, GSMEM);
    cudaFuncSetAttribute(gemm_o,   cudaFuncAttributeMaxDynamicSharedMemorySize, GSMEM);
    cudaFuncSetAttribute(attn_mma, cudaFuncAttributeMaxDynamicSharedMemorySize, ATSMEM);

    // fp32 -> bf16 hi/lo splits
    split_kernel<<<(MTOK*DM/4 + 255)/256, 256>>>(residual, Rh, Rl, MTOK*DM/4);
    split_kernel<<<(2048*DM/4 + 255)/256, 256>>>(W_Q, WQh, WQl, 2048*DM/4);
    split_kernel<<<(512*DM/4 + 255)/256, 256>>>(W_K, WKh, WKl, 512*DM/4);
    split_kernel<<<(512*DM/4 + 255)/256, 256>>>(W_V, WVh, WVl, 512*DM/4);
    transpose_split_kernel<<<dim3(64, 64), dim3(32, 8)>>>(W_O, WOTh, WOTl);

    // Merged QKV projections
    gemm_qkv<<<dim3(24, MTOK/128), 256, GSMEM>>>(Rh, Rl, WQh, WQl, WKh, WKl, WVh, WVl,
                                                 Qh, Ql, Kh, Kl, Vh, Vl);

    // Tensor-core flash attention (2 CTAs/SM)
    attn_mma<<<dim3(SS/128, NH, BB), 256, ATSMEM>>>(Qh, Ql, Kh, Kl, Vh, Vl, Ah, Al);

    // Output projection -> fp32 out
    gemm_o<<<dim3(2048/128, MTOK/128), 256, GSMEM>>>(Ah, Al, WOTh, WOTl, out);
}

// round 15
// speedup vs baseline: 1.2348x; 1.1880x over previous
#include <cuda_runtime.h>
#include <cuda_bf16.h>
#include <cuda_fp16.h>
#include <math.h>
#include <stdint.h>

// Problem constants
#define BB   2
#define SS   2048
#define DM   2048
#define NH   32
#define NKV  8
#define DH   64
#define MTOK (BB*SS)        // 4096 tokens

// ---------------------------------------------------------------------
// Scratch (device globals: allocation-free rule)
// ---------------------------------------------------------------------
__device__ __nv_bfloat16 g_Rh[MTOK * DM];
__device__ __nv_bfloat16 g_Rl[MTOK * DM];
__device__ __nv_bfloat16 g_WQh[2048 * DM];
__device__ __nv_bfloat16 g_WQl[2048 * DM];
__device__ __nv_bfloat16 g_WKh[512 * DM];
__device__ __nv_bfloat16 g_WKl[512 * DM];
__device__ __nv_bfloat16 g_WVh[512 * DM];
__device__ __nv_bfloat16 g_WVl[512 * DM];
__device__ __nv_bfloat16 g_WOTh[2048 * 2048];   // W_O transposed: [d][nh]
__device__ __nv_bfloat16 g_WOTl[2048 * 2048];

// projection outputs: fp16 (attention consumes single-term fp16)
__device__ __half g_Qf[MTOK * (NH*DH)];
__device__ __half g_Kf[MTOK * (NKV*DH)];
__device__ __half g_Vf[MTOK * (NKV*DH)];

// attention output, bf16 hi/lo (O-projection stays full split precision)
__device__ __nv_bfloat16 g_Ah[MTOK * (NH*DH)];
__device__ __nv_bfloat16 g_Al[MTOK * (NH*DH)];

// ---------------------------------------------------------------------
// helpers
// ---------------------------------------------------------------------
__device__ __forceinline__ uint32_t smem_u32(const void* p) {
    uint32_t a;
    asm("{ .reg .u64 t; cvta.to.shared.u64 t, %1; cvt.u32.u64 %0, t; }" : "=r"(a) : "l"(p));
    return a;
}
__device__ __forceinline__ void cp_async16(uint32_t dst, const void* src) {
    asm volatile("cp.async.cg.shared.global [%0], [%1], 16;" :: "r"(dst), "l"(src));
}
#define CP_COMMIT()  asm volatile("cp.async.commit_group;" ::: "memory")
#define CP_WAIT1()   asm volatile("cp.async.wait_group 1;" ::: "memory")

__device__ __forceinline__ void ldsm_x4(uint32_t addr, uint32_t& r0, uint32_t& r1,
                                        uint32_t& r2, uint32_t& r3) {
    asm volatile("ldmatrix.sync.aligned.m8n8.x4.shared.b16 {%0,%1,%2,%3}, [%4];"
                 : "=r"(r0), "=r"(r1), "=r"(r2), "=r"(r3) : "r"(addr));
}
__device__ __forceinline__ void ldsm_x4_t(uint32_t addr, uint32_t& r0, uint32_t& r1,
                                          uint32_t& r2, uint32_t& r3) {
    asm volatile("ldmatrix.sync.aligned.m8n8.x4.trans.shared.b16 {%0,%1,%2,%3}, [%4];"
                 : "=r"(r0), "=r"(r1), "=r"(r2), "=r"(r3) : "r"(addr));
}
__device__ __forceinline__ void mma_bf16(float* d, const uint32_t* a, uint32_t b0, uint32_t b1) {
    asm volatile(
        "mma.sync.aligned.m16n8k16.row.col.f32.bf16.bf16.f32 "
        "{%0,%1,%2,%3}, {%4,%5,%6,%7}, {%8,%9}, {%0,%1,%2,%3};"
        : "+f"(d[0]), "+f"(d[1]), "+f"(d[2]), "+f"(d[3])
        : "r"(a[0]), "r"(a[1]), "r"(a[2]), "r"(a[3]), "r"(b0), "r"(b1));
}
__device__ __forceinline__ void mma_f16(float* d, const uint32_t* a, uint32_t b0, uint32_t b1) {
    asm volatile(
        "mma.sync.aligned.m16n8k16.row.col.f32.f16.f16.f32 "
        "{%0,%1,%2,%3}, {%4,%5,%6,%7}, {%8,%9}, {%0,%1,%2,%3};"
        : "+f"(d[0]), "+f"(d[1]), "+f"(d[2]), "+f"(d[3])
        : "r"(a[0]), "r"(a[1]), "r"(a[2]), "r"(a[3]), "r"(b0), "r"(b1));
}
__device__ __forceinline__ float ex2(float x) {
    float y;
    asm("ex2.approx.f32 %0, %1;" : "=f"(y) : "f"(x));
    return y;
}
// packed bf16x2: {hi16=bf16(vhi), lo16=bf16(vlo)}
__device__ __forceinline__ uint32_t cvt_bf2(float vlo, float vhi) {
    uint32_t r;
    asm("cvt.rn.bf16x2.f32 %0, %1, %2;" : "=r"(r) : "f"(vhi), "f"(vlo));
    return r;
}
// packed f16x2: {hi16=f16(vhi), lo16=f16(vlo)}
__device__ __forceinline__ uint32_t cvt_f16x2(float vlo, float vhi) {
    uint32_t r;
    asm("cvt.rn.f16x2.f32 %0, %1, %2;" : "=r"(r) : "f"(vhi), "f"(vlo));
    return r;
}
// split a pair: bf16-hi-packed word + bf16-residual-packed word
__device__ __forceinline__ void split_pair(float v0, float v1, uint32_t& ph, uint32_t& pl) {
    ph = cvt_bf2(v0, v1);
    float h0 = __uint_as_float(ph << 16);
    float h1 = __uint_as_float(ph & 0xffff0000u);
    pl = cvt_bf2(v0 - h0, v1 - h1);
}
__device__ __forceinline__ void bsplit(float v, unsigned short& h, unsigned short& l) {
    __nv_bfloat16 bh = __float2bfloat16(v);
    float r = v - __bfloat162float(bh);
    __nv_bfloat16 bl = __float2bfloat16(r);
    h = *reinterpret_cast<unsigned short*>(&bh);
    l = *reinterpret_cast<unsigned short*>(&bl);
}

// ---------------------------------------------------------------------
// fp32 -> bf16 hi/lo split (inputs only)
// ---------------------------------------------------------------------
__global__ __launch_bounds__(256)
void split_kernel(const float* __restrict__ x, __nv_bfloat16* __restrict__ hi,
                  __nv_bfloat16* __restrict__ lo, int n4) {
    int i = blockIdx.x * 256 + threadIdx.x;
    if (i >= n4) return;
    float4 v = ((const float4*)x)[i];
    ushort4 h, l;
    bsplit(v.x, h.x, l.x); bsplit(v.y, h.y, l.y);
    bsplit(v.z, h.z, l.z); bsplit(v.w, h.w, l.w);
    ((ushort4*)hi)[i] = h;
    ((ushort4*)lo)[i] = l;
}

// W_O [nh=2048][d=2048] -> transposed split [d][nh]
__global__ __launch_bounds__(256)
void transpose_split_kernel(const float* __restrict__ W,
                            __nv_bfloat16* __restrict__ th,
                            __nv_bfloat16* __restrict__ tl) {
    __shared__ float t[32][33];
    int bx = blockIdx.x * 32, by = blockIdx.y * 32;
    int txx = threadIdx.x, tyy = threadIdx.y;   // block (32, 8)
    #pragma unroll
    for (int j = 0; j < 4; j++)
        t[tyy + 8*j][txx] = W[(size_t)(by + tyy + 8*j) * 2048 + bx + txx];
    __syncthreads();
    #pragma unroll
    for (int j = 0; j < 4; j++) {
        int orow = bx + tyy + 8*j;
        int ocol = by + txx;
        float v = t[txx][tyy + 8*j];
        unsigned short h, l;
        bsplit(v, h, l);
        th[(size_t)orow * 2048 + ocol] = *reinterpret_cast<__nv_bfloat16*>(&h);
        tl[(size_t)orow * 2048 + ocol] = *reinterpret_cast<__nv_bfloat16*>(&l);
    }
}

// ---------------------------------------------------------------------
// mma.sync bf16-split GEMM NT body
// OUT_MODE: 0 = fp32 C, 2 = fp16 single C
// ---------------------------------------------------------------------
#define BK        64
#define NKCHUNK   (DM / BK)          // 32
#define TILE_B    (128 * BK * 2)     // 16384
#define STG_B     (4 * TILE_B)       // 64KB
#define NSTAGE    3
#define GSMEM     (NSTAGE * STG_B)   // 192KB

template<int OUT_MODE>
__device__ __forceinline__
void gemm_body(const __nv_bfloat16* __restrict__ Ah, const __nv_bfloat16* __restrict__ Al,
               const __nv_bfloat16* __restrict__ Bh, const __nv_bfloat16* __restrict__ Bl,
               int row0, int col0,
               float* __restrict__ C, __half* __restrict__ Cf, int Ntot) {
    extern __shared__ char sm[];
    const uint32_t sb = smem_u32(sm);
    const int tid = threadIdx.x, wid = tid >> 5, lane = tid & 31;
    const int wm = (wid >> 2) * 64;
    const int wn = (wid & 3) * 32;

    const char* gAh = (const char*)Ah + (size_t)row0 * 4096;
    const char* gAl = (const char*)Al + (size_t)row0 * 4096;
    const char* gBh = (const char*)Bh + (size_t)col0 * 4096;
    const char* gBl = (const char*)Bl + (size_t)col0 * 4096;

    const int lrow = ((lane >> 3) & 1) * 8 + (lane & 7);
    const int lkb  = (lane >> 4) * 16;

    float acc[4][4][4];
    #pragma unroll
    for (int mt = 0; mt < 4; mt++)
        #pragma unroll
        for (int nt = 0; nt < 4; nt++)
            #pragma unroll
            for (int e = 0; e < 4; e++) acc[mt][nt][e] = 0.f;

    auto load_stage = [&](int stage, int chunk) {
        uint32_t s0 = sb + stage * STG_B;
        const size_t kb0 = (size_t)chunk * 128;
        #pragma unroll
        for (int t = 0; t < 4; t++) {
            int idx = tid + t * 256;
            int r = idx >> 3, g = idx & 7;
            uint32_t so = (uint32_t)(r * 128 + ((g * 16) ^ ((r & 7) << 4)));
            size_t go = (size_t)r * 4096 + kb0 + g * 16;
            cp_async16(s0 + 0*TILE_B + so, gAh + go);
            cp_async16(s0 + 1*TILE_B + so, gAl + go);
            cp_async16(s0 + 2*TILE_B + so, gBh + go);
            cp_async16(s0 + 3*TILE_B + so, gBl + go);
        }
    };

    load_stage(0, 0); CP_COMMIT();
    load_stage(1, 1); CP_COMMIT();

    for (int i = 0; i < NKCHUNK; i++) {
        CP_WAIT1();
        __syncthreads();
        if (i + 2 < NKCHUNK) load_stage((i + 2) % NSTAGE, i + 2);
        CP_COMMIT();

        uint32_t s0 = sb + (i % NSTAGE) * STG_B;
        uint32_t aH = s0 + 0*TILE_B, aL = s0 + 1*TILE_B;
        uint32_t bH = s0 + 2*TILE_B, bL = s0 + 3*TILE_B;

        #pragma unroll
        for (int ks = 0; ks < 4; ks++) {
            const int kb = ks * 32 + lkb;
            uint32_t ah[4][4], al[4][4];
            #pragma unroll
            for (int mt = 0; mt < 4; mt++) {
                int r = wm + mt * 16 + lrow;
                uint32_t off = (uint32_t)(r * 128 + (kb ^ ((r & 7) << 4)));
                ldsm_x4(aH + off, ah[mt][0], ah[mt][1], ah[mt][2], ah[mt][3]);
                ldsm_x4(aL + off, al[mt][0], al[mt][1], al[mt][2], al[mt][3]);
            }
            uint32_t bhr[2][4], blr[2][4];
            #pragma unroll
            for (int np = 0; np < 2; np++) {
                int r = wn + np * 16 + lrow;
                uint32_t off = (uint32_t)(r * 128 + (kb ^ ((r & 7) << 4)));
                ldsm_x4(bH + off, bhr[np][0], bhr[np][1], bhr[np][2], bhr[np][3]);
                ldsm_x4(bL + off, blr[np][0], blr[np][1], blr[np][2], blr[np][3]);
            }
            #pragma unroll
            for (int mt = 0; mt < 4; mt++) {
                #pragma unroll
                for (int nt = 0; nt < 4; nt++) {
                    uint32_t b0h = bhr[nt >> 1][nt & 1], b1h = bhr[nt >> 1][2 + (nt & 1)];
                    uint32_t b0l = blr[nt >> 1][nt & 1], b1l = blr[nt >> 1][2 + (nt & 1)];
                    mma_bf16(acc[mt][nt], ah[mt], b0h, b1h);
                    mma_bf16(acc[mt][nt], ah[mt], b0l, b1l);
                    mma_bf16(acc[mt][nt], al[mt], b0h, b1h);
                }
            }
        }
        __syncthreads();
    }

    #pragma unroll
    for (int mt = 0; mt < 4; mt++) {
        int m0 = row0 + wm + mt * 16 + (lane >> 2);
        #pragma unroll
        for (int nt = 0; nt < 4; nt++) {
            int n0 = col0 + wn + nt * 8 + (lane & 3) * 2;
            if (OUT_MODE == 2) {
                #pragma unroll
                for (int hh = 0; hh < 2; hh++) {
                    size_t idx = (size_t)(m0 + hh * 8) * Ntot + n0;
                    *(uint32_t*)&Cf[idx] = cvt_f16x2(acc[mt][nt][hh*2], acc[mt][nt][hh*2 + 1]);
                }
            } else {
                *(float2*)&C[(size_t)m0 * Ntot + n0]       = make_float2(acc[mt][nt][0], acc[mt][nt][1]);
                *(float2*)&C[(size_t)(m0 + 8) * Ntot + n0] = make_float2(acc[mt][nt][2], acc[mt][nt][3]);
            }
        }
    }
}

// Merged QKV (fp16 outputs): grid (24, 32). tiles 0-15 -> Q, 16-19 -> K, 20-23 -> V.
__global__ __launch_bounds__(256)
void gemm_qkv(const __nv_bfloat16* __restrict__ Rh, const __nv_bfloat16* __restrict__ Rl,
              const __nv_bfloat16* __restrict__ WQh, const __nv_bfloat16* __restrict__ WQl,
              const __nv_bfloat16* __restrict__ WKh, const __nv_bfloat16* __restrict__ WKl,
              const __nv_bfloat16* __restrict__ WVh, const __nv_bfloat16* __restrict__ WVl,
              __half* __restrict__ Qf, __half* __restrict__ Kf, __half* __restrict__ Vf) {
    const int ct = blockIdx.x, row0 = blockIdx.y * 128;
    const __nv_bfloat16 *bh, *bl;
    __half* cf;
    int n, c0;
    if (ct < 16)      { bh = WQh; bl = WQl; cf = Qf; n = 2048; c0 = ct * 128; }
    else if (ct < 20) { bh = WKh; bl = WKl; cf = Kf; n = 512;  c0 = (ct - 16) * 128; }
    else              { bh = WVh; bl = WVl; cf = Vf; n = 512;  c0 = (ct - 20) * 128; }
    gemm_body<2>(Rh, Rl, bh, bl, row0, c0, nullptr, cf, n);
}

// O projection: fp32 output, full split precision
__global__ __launch_bounds__(256)
void gemm_o(const __nv_bfloat16* __restrict__ Ah, const __nv_bfloat16* __restrict__ Al,
            const __nv_bfloat16* __restrict__ Bh, const __nv_bfloat16* __restrict__ Bl,
            float* __restrict__ C) {
    gemm_body<0>(Ah, Al, Bh, Bl, blockIdx.y * 128, blockIdx.x * 128, C, nullptr, 2048);
}

// =====================================================================
// Tensor-core flash attention: causal, GQA, SINGLE-TERM FP16.
// 128 Q rows per CTA, 8 warps x 16 rows. KV tiles of 64, double-buffered.
// smem: Q 16KB + 2 stages x (K 8KB + V 8KB) = 48KB.
// =====================================================================
#define ATQ    0
#define ATSTG(s) (16384 + (s)*16384)
#define ATK    0
#define ATV    8192
#define ATSMEM 49152
#define SCALE2 0.18033688f   // 0.125 * log2(e)

__global__ __launch_bounds__(256, 2)
void attn_mma(const __half* __restrict__ Qf, const __half* __restrict__ Kf,
              const __half* __restrict__ Vf,
              __nv_bfloat16* __restrict__ Oh, __nv_bfloat16* __restrict__ Ol) {
    extern __shared__ char sm[];
    const uint32_t sb = smem_u32(sm);
    const int tid = threadIdx.x, wid = tid >> 5, lane = tid & 31;
    const int qt = (int)gridDim.x - 1 - (int)blockIdx.x;   // heavy-first
    const int h = blockIdx.y, b = blockIdx.z;
    const int kvh = h >> 2;
    const int q0 = qt * 128;

    const char* gQ = (const char*)Qf + ((size_t)(b * SS + q0) * 2048 + h * 64) * 2;
    const char* gK = (const char*)Kf + ((size_t)b * SS * 512 + kvh * 64) * 2;
    const char* gV = (const char*)Vf + ((size_t)b * SS * 512 + kvh * 64) * 2;

    // Q tile: 128 rows x 128B
    #pragma unroll
    for (int t = 0; t < 4; t++) {
        int idx = tid + t * 256;
        int r = idx >> 3, g = idx & 7;
        uint32_t so = (uint32_t)(r * 128 + ((g * 16) ^ ((r & 7) << 4)));
        cp_async16(sb + ATQ + so, gQ + (size_t)r * 4096 + g * 16);
    }
    CP_COMMIT();

    auto load_kv = [&](int stage, int tile) {
        uint32_t s0 = sb + ATSTG(stage);
        #pragma unroll
        for (int t = 0; t < 2; t++) {
            int idx = tid + t * 256;
            int r = idx >> 3, g = idx & 7;
            uint32_t so = (uint32_t)(r * 128 + ((g * 16) ^ ((r & 7) << 4)));
            size_t go = (size_t)(tile * 64 + r) * 1024 + g * 16;
            cp_async16(s0 + ATK + so, gK + go);
            cp_async16(s0 + ATV + so, gV + go);
        }
    };

    const int ntiles = 2 * qt + 2;
    load_kv(0, 0); CP_COMMIT();
    load_kv(1, 1); CP_COMMIT();

    float m0 = -1e30f, m1 = -1e30f, l0 = 0.f, l1 = 0.f;
    float oacc[8][4];
    #pragma unroll
    for (int nt = 0; nt < 8; nt++)
        #pragma unroll
        for (int e = 0; e < 4; e++) oacc[nt][e] = 0.f;

    const int lrow = ((lane >> 3) & 1) * 8 + (lane & 7);
    const int lkb  = (lane >> 4) * 16;
    const int row0 = q0 + wid * 16 + (lane >> 2);
    const int row1 = row0 + 8;
    const int qr = wid * 16 + lrow;

    for (int j = 0; j < ntiles; j++) {
        CP_WAIT1();
        __syncthreads();

        uint32_t stg = sb + ATSTG(j & 1);

        // ---- S = Q K^T (fp16 single-term) ----
        float sacc[8][4];
        #pragma unroll
        for (int nt = 0; nt < 8; nt++)
            #pragma unroll
            for (int e = 0; e < 4; e++) sacc[nt][e] = 0.f;

        #pragma unroll
        for (int kc = 0; kc < 4; kc++) {
            const int kb = kc * 32 + lkb;
            uint32_t qoff = (uint32_t)(qr * 128 + (kb ^ ((qr & 7) << 4)));
            uint32_t qf[4];
            ldsm_x4(sb + ATQ + qoff, qf[0], qf[1], qf[2], qf[3]);
            #pragma unroll
            for (int np = 0; np < 4; np++) {
                int r = np * 16 + lrow;
                uint32_t off = (uint32_t)(r * 128 + (kb ^ ((r & 7) << 4)));
                uint32_t k0r, k1r, k2r, k3r;
                ldsm_x4(stg + ATK + off, k0r, k1r, k2r, k3r);
                mma_f16(sacc[np*2+0], qf, k0r, k2r);
                mma_f16(sacc[np*2+1], qf, k1r, k3r);
            }
        }

        // ---- scale (exp2 domain) + causal mask ----
        const int tok0 = j * 64;
        #pragma unroll
        for (int nt = 0; nt < 8; nt++)
            #pragma unroll
            for (int e = 0; e < 4; e++) sacc[nt][e] *= SCALE2;
        if (j >= 2 * qt) {
            #pragma unroll
            for (int nt = 0; nt < 8; nt++) {
                int colb = tok0 + nt * 8 + (lane & 3) * 2;
                if (colb     > row0) sacc[nt][0] = -1e30f;
                if (colb + 1 > row0) sacc[nt][1] = -1e30f;
                if (colb     > row1) sacc[nt][2] = -1e30f;
                if (colb + 1 > row1) sacc[nt][3] = -1e30f;
            }
        }

        // ---- online softmax (base-2) ----
        float mx0 = -1e30f, mx1 = -1e30f;
        #pragma unroll
        for (int nt = 0; nt < 8; nt++) {
            mx0 = fmaxf(mx0, fmaxf(sacc[nt][0], sacc[nt][1]));
            mx1 = fmaxf(mx1, fmaxf(sacc[nt][2], sacc[nt][3]));
        }
        mx0 = fmaxf(mx0, __shfl_xor_sync(0xffffffffu, mx0, 1));
        mx0 = fmaxf(mx0, __shfl_xor_sync(0xffffffffu, mx0, 2));
        mx1 = fmaxf(mx1, __shfl_xor_sync(0xffffffffu, mx1, 1));
        mx1 = fmaxf(mx1, __shfl_xor_sync(0xffffffffu, mx1, 2));
        float mn0 = fmaxf(m0, mx0), mn1 = fmaxf(m1, mx1);
        float a0 = ex2(m0 - mn0), a1 = ex2(m1 - mn1);
        m0 = mn0; m1 = mn1;

        float rs0 = 0.f, rs1 = 0.f;
        #pragma unroll
        for (int nt = 0; nt < 8; nt++) {
            sacc[nt][0] = ex2(sacc[nt][0] - mn0);
            sacc[nt][1] = ex2(sacc[nt][1] - mn0);
            sacc[nt][2] = ex2(sacc[nt][2] - mn1);
            sacc[nt][3] = ex2(sacc[nt][3] - mn1);
            rs0 += sacc[nt][0] + sacc[nt][1];
            rs1 += sacc[nt][2] + sacc[nt][3];
        }
        rs0 += __shfl_xor_sync(0xffffffffu, rs0, 1);
        rs0 += __shfl_xor_sync(0xffffffffu, rs0, 2);
        rs1 += __shfl_xor_sync(0xffffffffu, rs1, 1);
        rs1 += __shfl_xor_sync(0xffffffffu, rs1, 2);
        l0 = l0 * a0 + rs0;
        l1 = l1 * a1 + rs1;

        #pragma unroll
        for (int nt = 0; nt < 8; nt++) {
            oacc[nt][0] *= a0; oacc[nt][1] *= a0;
            oacc[nt][2] *= a1; oacc[nt][3] *= a1;
        }

        // ---- O += P V (fp16 single-term; P packed via cvt.rn.f16x2) ----
        #pragma unroll
        for (int tc = 0; tc < 4; tc++) {
            uint32_t pf[4];
            #pragma unroll
            for (int q = 0; q < 4; q++) {
                const int nt = tc * 2 + (q >> 1);
                const int e0 = (q & 1) * 2;
                int slot = (q >> 1) * 2 + (q & 1);
                pf[slot] = cvt_f16x2(sacc[nt][e0], sacc[nt][e0 + 1]);
            }
            #pragma unroll
            for (int nh = 0; nh < 4; nh++) {
                int r = tc * 16 + lrow;
                uint32_t off = (uint32_t)(r * 128 + ((nh * 32 + lkb) ^ ((r & 7) << 4)));
                uint32_t v0r, v1r, v2r, v3r;
                ldsm_x4_t(stg + ATV + off, v0r, v1r, v2r, v3r);
                mma_f16(oacc[nh*2+0], pf, v0r, v1r);
                mma_f16(oacc[nh*2+1], pf, v2r, v3r);
            }
        }

        __syncthreads();
        if (j + 2 < ntiles) load_kv(j & 1, j + 2);
        CP_COMMIT();
    }

    // ---- epilogue: normalize, split to bf16 hi/lo for O-projection ----
    float inv0 = 1.f / l0, inv1 = 1.f / l1;
    #pragma unroll
    for (int nt = 0; nt < 8; nt++) {
        int col = nt * 8 + (lane & 3) * 2;
        #pragma unroll
        for (int hh = 0; hh < 2; hh++) {
            int grow = (hh == 0) ? row0 : row1;
            float inv = (hh == 0) ? inv0 : inv1;
            size_t idx = (size_t)(b * SS + grow) * 2048 + h * 64 + col;
            uint32_t ph, pl;
            split_pair(oacc[nt][hh*2] * inv, oacc[nt][hh*2 + 1] * inv, ph, pl);
            *(uint32_t*)&Oh[idx] = ph;
            *(uint32_t*)&Ol[idx] = pl;
        }
    }
}

// =====================================================================
// Host launcher
// =====================================================================
extern "C" void kernel_launch(void* const* d_in, const int* in_sizes, int n_in,
                              void* d_out, int out_size) {
    const float* residual = (const float*)d_in[0];
    const float* W_Q = (const float*)d_in[1];
    const float* W_K = (const float*)d_in[2];
    const float* W_V = (const float*)d_in[3];
    const float* W_O = (const float*)d_in[4];
    float* out = (float*)d_out;

    __nv_bfloat16 *Rh, *Rl, *WQh, *WQl, *WKh, *WKl, *WVh, *WVl, *WOTh, *WOTl, *Ah, *Al;
    __half *Qf, *Kf, *Vf;
    cudaGetSymbolAddress((void**)&Rh,  g_Rh);   cudaGetSymbolAddress((void**)&Rl,  g_Rl);
    cudaGetSymbolAddress((void**)&WQh, g_WQh);  cudaGetSymbolAddress((void**)&WQl, g_WQl);
    cudaGetSymbolAddress((void**)&WKh, g_WKh);  cudaGetSymbolAddress((void**)&WKl, g_WKl);
    cudaGetSymbolAddress((void**)&WVh, g_WVh);  cudaGetSymbolAddress((void**)&WVl, g_WVl);
    cudaGetSymbolAddress((void**)&WOTh, g_WOTh); cudaGetSymbolAddress((void**)&WOTl, g_WOTl);
    cudaGetSymbolAddress((void**)&Qf, g_Qf);
    cudaGetSymbolAddress((void**)&Kf, g_Kf);
    cudaGetSymbolAddress((void**)&Vf, g_Vf);
    cudaGetSymbolAddress((void**)&Ah, g_Ah);    cudaGetSymbolAddress((void**)&Al, g_Al);

    cudaFuncSetAttribute(gemm_qkv, cudaFuncAttributeMaxDynamicSharedMemorySize, GSMEM);
    cudaFuncSetAttribute(gemm_o,   cudaFuncAttributeMaxDynamicSharedMemorySize, GSMEM);
    cudaFuncSetAttribute(attn_mma, cudaFuncAttributeMaxDynamicSharedMemorySize, ATSMEM);

    // fp32 -> bf16 hi/lo splits
    split_kernel<<<(MTOK*DM/4 + 255)/256, 256>>>(residual, Rh, Rl, MTOK*DM/4);
    split_kernel<<<(2048*DM/4 + 255)/256, 256>>>(W_Q, WQh, WQl, 2048*DM/4);
    split_kernel<<<(512*DM/4 + 255)/256, 256>>>(W_K, WKh, WKl, 512*DM/4);
    split_kernel<<<(512*DM/4 + 255)/256, 256>>>(W_V, WVh, WVl, 512*DM/4);
    transpose_split_kernel<<<dim3(64, 64), dim3(32, 8)>>>(W_O, WOTh, WOTl);

    // Merged QKV projections -> fp16 outputs
    gemm_qkv<<<dim3(24, MTOK/128), 256, GSMEM>>>(Rh, Rl, WQh, WQl, WKh, WKl, WVh, WVl,
                                                 Qf, Kf, Vf);

    // Tensor-core flash attention (fp16 single-term)
    attn_mma<<<dim3(SS/128, NH, BB), 256, ATSMEM>>>(Qf, Kf, Vf, Ah, Al);

    // Output projection -> fp32 out (full split precision)
    gemm_o<<<dim3(2048/128, MTOK/128), 256, GSMEM>>>(Ah, Al, WOTh, WOTl, out);
}

// round 16
// speedup vs baseline: 2.6764x; 2.1675x over previous
#include <cuda_runtime.h>
#include <cuda_bf16.h>
#include <cuda_fp16.h>
#include <math.h>
#include <stdint.h>

// Problem constants
#define BB   2
#define SS   2048
#define DM   2048
#define NH   32
#define NKV  8
#define DH   64
#define MTOK (BB*SS)        // 4096 tokens

// ---------------------------------------------------------------------
// Scratch (device globals: allocation-free rule) — all fp16 now
// ---------------------------------------------------------------------
__device__ __half g_Rf[MTOK * DM];
__device__ __half g_WQf[2048 * DM];
__device__ __half g_WKf[512 * DM];
__device__ __half g_WVf[512 * DM];
__device__ __half g_WOTf[2048 * 2048];   // W_O transposed: [d][nh]

__device__ __half g_Qf[MTOK * (NH*DH)];
__device__ __half g_Kf[MTOK * (NKV*DH)];
__device__ __half g_Vf[MTOK * (NKV*DH)];
__device__ __half g_Af[MTOK * (NH*DH)];

// ---------------------------------------------------------------------
// helpers
// ---------------------------------------------------------------------
__device__ __forceinline__ uint32_t smem_u32(const void* p) {
    uint32_t a;
    asm("{ .reg .u64 t; cvta.to.shared.u64 t, %1; cvt.u32.u64 %0, t; }" : "=r"(a) : "l"(p));
    return a;
}
__device__ __forceinline__ void cp_async16(uint32_t dst, const void* src) {
    asm volatile("cp.async.cg.shared.global [%0], [%1], 16;" :: "r"(dst), "l"(src));
}
#define CP_COMMIT()  asm volatile("cp.async.commit_group;" ::: "memory")
#define CP_WAIT1()   asm volatile("cp.async.wait_group 1;" ::: "memory")

__device__ __forceinline__ void ldsm_x4(uint32_t addr, uint32_t& r0, uint32_t& r1,
                                        uint32_t& r2, uint32_t& r3) {
    asm volatile("ldmatrix.sync.aligned.m8n8.x4.shared.b16 {%0,%1,%2,%3}, [%4];"
                 : "=r"(r0), "=r"(r1), "=r"(r2), "=r"(r3) : "r"(addr));
}
__device__ __forceinline__ void ldsm_x4_t(uint32_t addr, uint32_t& r0, uint32_t& r1,
                                          uint32_t& r2, uint32_t& r3) {
    asm volatile("ldmatrix.sync.aligned.m8n8.x4.trans.shared.b16 {%0,%1,%2,%3}, [%4];"
                 : "=r"(r0), "=r"(r1), "=r"(r2), "=r"(r3) : "r"(addr));
}
__device__ __forceinline__ void mma_f16(float* d, const uint32_t* a, uint32_t b0, uint32_t b1) {
    asm volatile(
        "mma.sync.aligned.m16n8k16.row.col.f32.f16.f16.f32 "
        "{%0,%1,%2,%3}, {%4,%5,%6,%7}, {%8,%9}, {%0,%1,%2,%3};"
        : "+f"(d[0]), "+f"(d[1]), "+f"(d[2]), "+f"(d[3])
        : "r"(a[0]), "r"(a[1]), "r"(a[2]), "r"(a[3]), "r"(b0), "r"(b1));
}
__device__ __forceinline__ float ex2(float x) {
    float y;
    asm("ex2.approx.f32 %0, %1;" : "=f"(y) : "f"(x));
    return y;
}
// packed f16x2: {hi16=f16(vhi), lo16=f16(vlo)}
__device__ __forceinline__ uint32_t cvt_f16x2(float vlo, float vhi) {
    uint32_t r;
    asm("cvt.rn.f16x2.f32 %0, %1, %2;" : "=r"(r) : "f"(vhi), "f"(vlo));
    return r;
}

// ---------------------------------------------------------------------
// fp32 -> fp16 convert
// ---------------------------------------------------------------------
__global__ __launch_bounds__(256)
void convert_kernel(const float* __restrict__ x, __half* __restrict__ y, int n4) {
    int i = blockIdx.x * 256 + threadIdx.x;
    if (i >= n4) return;
    float4 v = ((const float4*)x)[i];
    uint2 o;
    o.x = cvt_f16x2(v.x, v.y);
    o.y = cvt_f16x2(v.z, v.w);
    ((uint2*)y)[i] = o;
}

// W_O [nh=2048][d=2048] -> transposed fp16 [d][nh]
__global__ __launch_bounds__(256)
void transpose_convert_kernel(const float* __restrict__ W, __half* __restrict__ T) {
    __shared__ float t[32][33];
    int bx = blockIdx.x * 32, by = blockIdx.y * 32;
    int txx = threadIdx.x, tyy = threadIdx.y;   // block (32, 8)
    #pragma unroll
    for (int j = 0; j < 4; j++)
        t[tyy + 8*j][txx] = W[(size_t)(by + tyy + 8*j) * 2048 + bx + txx];
    __syncthreads();
    #pragma unroll
    for (int j = 0; j < 4; j++) {
        int orow = bx + tyy + 8*j;
        int ocol = by + txx;
        T[(size_t)orow * 2048 + ocol] = __float2half(t[txx][tyy + 8*j]);
    }
}

// ---------------------------------------------------------------------
// mma.sync single-term fp16 GEMM NT body
// C[128,128] tile = A[128,K] @ B[128,K]^T, K=2048.
// OUT_MODE: 0 = fp32 C, 2 = fp16 C
// ---------------------------------------------------------------------
#define BK        64
#define NKCHUNK   (DM / BK)          // 32
#define TILE_B    (128 * BK * 2)     // 16384
#define STG_B     (2 * TILE_B)       // 32KB (A + B)
#define NSTAGE    3
#define GSMEM     (NSTAGE * STG_B)   // 96KB

template<int OUT_MODE>
__device__ __forceinline__
void gemm_body(const __half* __restrict__ A, const __half* __restrict__ B,
               int row0, int col0,
               float* __restrict__ C, __half* __restrict__ Cf, int Ntot) {
    extern __shared__ char sm[];
    const uint32_t sb = smem_u32(sm);
    const int tid = threadIdx.x, wid = tid >> 5, lane = tid & 31;
    const int wm = (wid >> 2) * 64;
    const int wn = (wid & 3) * 32;

    const char* gA = (const char*)A + (size_t)row0 * 4096;
    const char* gB = (const char*)B + (size_t)col0 * 4096;

    const int lrow = ((lane >> 3) & 1) * 8 + (lane & 7);
    const int lkb  = (lane >> 4) * 16;

    float acc[4][4][4];
    #pragma unroll
    for (int mt = 0; mt < 4; mt++)
        #pragma unroll
        for (int nt = 0; nt < 4; nt++)
            #pragma unroll
            for (int e = 0; e < 4; e++) acc[mt][nt][e] = 0.f;

    auto load_stage = [&](int stage, int chunk) {
        uint32_t s0 = sb + stage * STG_B;
        const size_t kb0 = (size_t)chunk * 128;
        #pragma unroll
        for (int t = 0; t < 4; t++) {
            int idx = tid + t * 256;
            int r = idx >> 3, g = idx & 7;
            uint32_t so = (uint32_t)(r * 128 + ((g * 16) ^ ((r & 7) << 4)));
            size_t go = (size_t)r * 4096 + kb0 + g * 16;
            cp_async16(s0 + 0*TILE_B + so, gA + go);
            cp_async16(s0 + 1*TILE_B + so, gB + go);
        }
    };

    load_stage(0, 0); CP_COMMIT();
    load_stage(1, 1); CP_COMMIT();

    for (int i = 0; i < NKCHUNK; i++) {
        CP_WAIT1();
        __syncthreads();
        if (i + 2 < NKCHUNK) load_stage((i + 2) % NSTAGE, i + 2);
        CP_COMMIT();

        uint32_t s0 = sb + (i % NSTAGE) * STG_B;
        uint32_t aT = s0 + 0*TILE_B, bT = s0 + 1*TILE_B;

        #pragma unroll
        for (int ks = 0; ks < 4; ks++) {
            const int kb = ks * 32 + lkb;
            uint32_t af[4][4];
            #pragma unroll
            for (int mt = 0; mt < 4; mt++) {
                int r = wm + mt * 16 + lrow;
                uint32_t off = (uint32_t)(r * 128 + (kb ^ ((r & 7) << 4)));
                ldsm_x4(aT + off, af[mt][0], af[mt][1], af[mt][2], af[mt][3]);
            }
            uint32_t br[2][4];
            #pragma unroll
            for (int np = 0; np < 2; np++) {
                int r = wn + np * 16 + lrow;
                uint32_t off = (uint32_t)(r * 128 + (kb ^ ((r & 7) << 4)));
                ldsm_x4(bT + off, br[np][0], br[np][1], br[np][2], br[np][3]);
            }
            #pragma unroll
            for (int mt = 0; mt < 4; mt++) {
                #pragma unroll
                for (int nt = 0; nt < 4; nt++) {
                    uint32_t b0 = br[nt >> 1][nt & 1], b1 = br[nt >> 1][2 + (nt & 1)];
                    mma_f16(acc[mt][nt], af[mt], b0, b1);
                }
            }
        }
        __syncthreads();
    }

    #pragma unroll
    for (int mt = 0; mt < 4; mt++) {
        int m0 = row0 + wm + mt * 16 + (lane >> 2);
        #pragma unroll
        for (int nt = 0; nt < 4; nt++) {
            int n0 = col0 + wn + nt * 8 + (lane & 3) * 2;
            if (OUT_MODE == 2) {
                #pragma unroll
                for (int hh = 0; hh < 2; hh++) {
                    size_t idx = (size_t)(m0 + hh * 8) * Ntot + n0;
                    *(uint32_t*)&Cf[idx] = cvt_f16x2(acc[mt][nt][hh*2], acc[mt][nt][hh*2 + 1]);
                }
            } else {
                *(float2*)&C[(size_t)m0 * Ntot + n0]       = make_float2(acc[mt][nt][0], acc[mt][nt][1]);
                *(float2*)&C[(size_t)(m0 + 8) * Ntot + n0] = make_float2(acc[mt][nt][2], acc[mt][nt][3]);
            }
        }
    }
}

// Merged QKV (fp16 outputs): grid (24, 32). tiles 0-15 -> Q, 16-19 -> K, 20-23 -> V.
__global__ __launch_bounds__(256)
void gemm_qkv(const __half* __restrict__ Rf,
              const __half* __restrict__ WQf, const __half* __restrict__ WKf,
              const __half* __restrict__ WVf,
              __half* __restrict__ Qf, __half* __restrict__ Kf, __half* __restrict__ Vf) {
    const int ct = blockIdx.x, row0 = blockIdx.y * 128;
    const __half* bm;
    __half* cf;
    int n, c0;
    if (ct < 16)      { bm = WQf; cf = Qf; n = 2048; c0 = ct * 128; }
    else if (ct < 20) { bm = WKf; cf = Kf; n = 512;  c0 = (ct - 16) * 128; }
    else              { bm = WVf; cf = Vf; n = 512;  c0 = (ct - 20) * 128; }
    gemm_body<2>(Rf, bm, row0, c0, nullptr, cf, n);
}

// O projection: fp32 output
__global__ __launch_bounds__(256)
void gemm_o(const __half* __restrict__ Af, const __half* __restrict__ WOTf,
            float* __restrict__ C) {
    gemm_body<0>(Af, WOTf, blockIdx.y * 128, blockIdx.x * 128, C, nullptr, 2048);
}

// =====================================================================
// Tensor-core flash attention: causal, GQA, single-term fp16.
// 128 Q rows per CTA, 8 warps x 16 rows. KV tiles of 64, double-buffered.
// smem: Q 16KB + 2 stages x (K 8KB + V 8KB) = 48KB.
// =====================================================================
#define ATQ    0
#define ATSTG(s) (16384 + (s)*16384)
#define ATK    0
#define ATV    8192
#define ATSMEM 49152
#define SCALE2 0.18033688f   // 0.125 * log2(e)

__global__ __launch_bounds__(256, 2)
void attn_mma(const __half* __restrict__ Qf, const __half* __restrict__ Kf,
              const __half* __restrict__ Vf, __half* __restrict__ Af) {
    extern __shared__ char sm[];
    const uint32_t sb = smem_u32(sm);
    const int tid = threadIdx.x, wid = tid >> 5, lane = tid & 31;
    const int qt = (int)gridDim.x - 1 - (int)blockIdx.x;   // heavy-first
    const int h = blockIdx.y, b = blockIdx.z;
    const int kvh = h >> 2;
    const int q0 = qt * 128;

    const char* gQ = (const char*)Qf + ((size_t)(b * SS + q0) * 2048 + h * 64) * 2;
    const char* gK = (const char*)Kf + ((size_t)b * SS * 512 + kvh * 64) * 2;
    const char* gV = (const char*)Vf + ((size_t)b * SS * 512 + kvh * 64) * 2;

    #pragma unroll
    for (int t = 0; t < 4; t++) {
        int idx = tid + t * 256;
        int r = idx >> 3, g = idx & 7;
        uint32_t so = (uint32_t)(r * 128 + ((g * 16) ^ ((r & 7) << 4)));
        cp_async16(sb + ATQ + so, gQ + (size_t)r * 4096 + g * 16);
    }
    CP_COMMIT();

    auto load_kv = [&](int stage, int tile) {
        uint32_t s0 = sb + ATSTG(stage);
        #pragma unroll
        for (int t = 0; t < 2; t++) {
            int idx = tid + t * 256;
            int r = idx >> 3, g = idx & 7;
            uint32_t so = (uint32_t)(r * 128 + ((g * 16) ^ ((r & 7) << 4)));
            size_t go = (size_t)(tile * 64 + r) * 1024 + g * 16;
            cp_async16(s0 + ATK + so, gK + go);
            cp_async16(s0 + ATV + so, gV + go);
        }
    };

    const int ntiles = 2 * qt + 2;
    load_kv(0, 0); CP_COMMIT();
    load_kv(1, 1); CP_COMMIT();

    float m0 = -1e30f, m1 = -1e30f, l0 = 0.f, l1 = 0.f;
    float oacc[8][4];
    #pragma unroll
    for (int nt = 0; nt < 8; nt++)
        #pragma unroll
        for (int e = 0; e < 4; e++) oacc[nt][e] = 0.f;

    const int lrow = ((lane >> 3) & 1) * 8 + (lane & 7);
    const int lkb  = (lane >> 4) * 16;
    const int row0 = q0 + wid * 16 + (lane >> 2);
    const int row1 = row0 + 8;
    const int qr = wid * 16 + lrow;

    for (int j = 0; j < ntiles; j++) {
        CP_WAIT1();
        __syncthreads();

        uint32_t stg = sb + ATSTG(j & 1);

        // ---- S = Q K^T ----
        float sacc[8][4];
        #pragma unroll
        for (int nt = 0; nt < 8; nt++)
            #pragma unroll
            for (int e = 0; e < 4; e++) sacc[nt][e] = 0.f;

        #pragma unroll
        for (int kc = 0; kc < 4; kc++) {
            const int kb = kc * 32 + lkb;
            uint32_t qoff = (uint32_t)(qr * 128 + (kb ^ ((qr & 7) << 4)));
            uint32_t qf[4];
            ldsm_x4(sb + ATQ + qoff, qf[0], qf[1], qf[2], qf[3]);
            #pragma unroll
            for (int np = 0; np < 4; np++) {
                int r = np * 16 + lrow;
                uint32_t off = (uint32_t)(r * 128 + (kb ^ ((r & 7) << 4)));
                uint32_t k0r, k1r, k2r, k3r;
                ldsm_x4(stg + ATK + off, k0r, k1r, k2r, k3r);
                mma_f16(sacc[np*2+0], qf, k0r, k2r);
                mma_f16(sacc[np*2+1], qf, k1r, k3r);
            }
        }

        // ---- scale (exp2 domain) + causal mask ----
        const int tok0 = j * 64;
        #pragma unroll
        for (int nt = 0; nt < 8; nt++)
            #pragma unroll
            for (int e = 0; e < 4; e++) sacc[nt][e] *= SCALE2;
        if (j >= 2 * qt) {
            #pragma unroll
            for (int nt = 0; nt < 8; nt++) {
                int colb = tok0 + nt * 8 + (lane & 3) * 2;
                if (colb     > row0) sacc[nt][0] = -1e30f;
                if (colb + 1 > row0) sacc[nt][1] = -1e30f;
                if (colb     > row1) sacc[nt][2] = -1e30f;
                if (colb + 1 > row1) sacc[nt][3] = -1e30f;
            }
        }

        // ---- online softmax (base-2) ----
        float mx0 = -1e30f, mx1 = -1e30f;
        #pragma unroll
        for (int nt = 0; nt < 8; nt++) {
            mx0 = fmaxf(mx0, fmaxf(sacc[nt][0], sacc[nt][1]));
            mx1 = fmaxf(mx1, fmaxf(sacc[nt][2], sacc[nt][3]));
        }
        mx0 = fmaxf(mx0, __shfl_xor_sync(0xffffffffu, mx0, 1));
        mx0 = fmaxf(mx0, __shfl_xor_sync(0xffffffffu, mx0, 2));
        mx1 = fmaxf(mx1, __shfl_xor_sync(0xffffffffu, mx1, 1));
        mx1 = fmaxf(mx1, __shfl_xor_sync(0xffffffffu, mx1, 2));
        float mn0 = fmaxf(m0, mx0), mn1 = fmaxf(m1, mx1);
        float a0 = ex2(m0 - mn0), a1 = ex2(m1 - mn1);
        m0 = mn0; m1 = mn1;

        float rs0 = 0.f, rs1 = 0.f;
        #pragma unroll
        for (int nt = 0; nt < 8; nt++) {
            sacc[nt][0] = ex2(sacc[nt][0] - mn0);
            sacc[nt][1] = ex2(sacc[nt][1] - mn0);
            sacc[nt][2] = ex2(sacc[nt][2] - mn1);
            sacc[nt][3] = ex2(sacc[nt][3] - mn1);
            rs0 += sacc[nt][0] + sacc[nt][1];
            rs1 += sacc[nt][2] + sacc[nt][3];
        }
        rs0 += __shfl_xor_sync(0xffffffffu, rs0, 1);
        rs0 += __shfl_xor_sync(0xffffffffu, rs0, 2);
        rs1 += __shfl_xor_sync(0xffffffffu, rs1, 1);
        rs1 += __shfl_xor_sync(0xffffffffu, rs1, 2);
        l0 = l0 * a0 + rs0;
        l1 = l1 * a1 + rs1;

        #pragma unroll
        for (int nt = 0; nt < 8; nt++) {
            oacc[nt][0] *= a0; oacc[nt][1] *= a0;
            oacc[nt][2] *= a1; oacc[nt][3] *= a1;
        }

        // ---- O += P V ----
        #pragma unroll
        for (int tc = 0; tc < 4; tc++) {
            uint32_t pf[4];
            #pragma unroll
            for (int q = 0; q < 4; q++) {
                const int nt = tc * 2 + (q >> 1);
                const int e0 = (q & 1) * 2;
                int slot = (q >> 1) * 2 + (q & 1);
                pf[slot] = cvt_f16x2(sacc[nt][e0], sacc[nt][e0 + 1]);
            }
            #pragma unroll
            for (int nh = 0; nh < 4; nh++) {
                int r = tc * 16 + lrow;
                uint32_t off = (uint32_t)(r * 128 + ((nh * 32 + lkb) ^ ((r & 7) << 4)));
                uint32_t v0r, v1r, v2r, v3r;
                ldsm_x4_t(stg + ATV + off, v0r, v1r, v2r, v3r);
                mma_f16(oacc[nh*2+0], pf, v0r, v1r);
                mma_f16(oacc[nh*2+1], pf, v2r, v3r);
            }
        }

        __syncthreads();
        if (j + 2 < ntiles) load_kv(j & 1, j + 2);
        CP_COMMIT();
    }

    // ---- epilogue: normalize, write fp16 ----
    float inv0 = 1.f / l0, inv1 = 1.f / l1;
    #pragma unroll
    for (int nt = 0; nt < 8; nt++) {
        int col = nt * 8 + (lane & 3) * 2;
        #pragma unroll
        for (int hh = 0; hh < 2; hh++) {
            int grow = (hh == 0) ? row0 : row1;
            float inv = (hh == 0) ? inv0 : inv1;
            size_t idx = (size_t)(b * SS + grow) * 2048 + h * 64 + col;
            *(uint32_t*)&Af[idx] = cvt_f16x2(oacc[nt][hh*2] * inv, oacc[nt][hh*2 + 1] * inv);
        }
    }
}

// =====================================================================
// Host launcher
// =====================================================================
extern "C" void kernel_launch(void* const* d_in, const int* in_sizes, int n_in,
                              void* d_out, int out_size) {
    const float* residual = (const float*)d_in[0];
    const float* W_Q = (const float*)d_in[1];
    const float* W_K = (const float*)d_in[2];
    const float* W_V = (const float*)d_in[3];
    const float* W_O = (const float*)d_in[4];
    float* out = (float*)d_out;

    __half *Rf, *WQf, *WKf, *WVf, *WOTf, *Qf, *Kf, *Vf, *Af;
    cudaGetSymbolAddress((void**)&Rf,  g_Rf);
    cudaGetSymbolAddress((void**)&WQf, g_WQf);
    cudaGetSymbolAddress((void**)&WKf, g_WKf);
    cudaGetSymbolAddress((void**)&WVf, g_WVf);
    cudaGetSymbolAddress((void**)&WOTf, g_WOTf);
    cudaGetSymbolAddress((void**)&Qf, g_Qf);
    cudaGetSymbolAddress((void**)&Kf, g_Kf);
    cudaGetSymbolAddress((void**)&Vf, g_Vf);
    cudaGetSymbolAddress((void**)&Af, g_Af);

    cudaFuncSetAttribute(gemm_qkv, cudaFuncAttributeMaxDynamicSharedMemorySize, GSMEM);
    cudaFuncSetAttribute(gemm_o,   cudaFuncAttributeMaxDynamicSharedMemorySize, GSMEM);
    cudaFuncSetAttribute(attn_mma, cudaFuncAttributeMaxDynamicSharedMemorySize, ATSMEM);

    // fp32 -> fp16 converts
    convert_kernel<<<(MTOK*DM/4 + 255)/256, 256>>>(residual, Rf, MTOK*DM/4);
    convert_kernel<<<(2048*DM/4 + 255)/256, 256>>>(W_Q, WQf, 2048*DM/4);
    convert_kernel<<<(512*DM/4 + 255)/256, 256>>>(W_K, WKf, 512*DM/4);
    convert_kernel<<<(512*DM/4 + 255)/256, 256>>>(W_V, WVf, 512*DM/4);
    transpose_convert_kernel<<<dim3(64, 64), dim3(32, 8)>>>(W_O, WOTf);

    // Merged QKV projections (single-term fp16)
    gemm_qkv<<<dim3(24, MTOK/128), 256, GSMEM>>>(Rf, WQf, WKf, WVf, Qf, Kf, Vf);

    // Tensor-core flash attention
    attn_mma<<<dim3(SS/128, NH, BB), 256, ATSMEM>>>(Qf, Kf, Vf, Af);

    // Output projection -> fp32 out
    gemm_o<<<dim3(2048/128, MTOK/128), 256, GSMEM>>>(Af, WOTf, out);
}